// round 13
// baseline (speedup 1.0000x reference)
#include <cuda_runtime.h>
#include <cuda_bf16.h>
#include <math.h>
#include <stdint.h>
#include <stddef.h>

// Problem dims (fixed)
#define TT 2048
#define BB 2
#define CC 512
#define HH 8
#define HDD 64
#define FF 2048
#define NLAYER 4
#define MR (TT*BB)
#define BHH (BB*HH)

#define BM 128
#define GBN 64
#define BK 32

// GEMM smem (swizzled, no padding): Ah 8KB, Al 8KB, Bh 4KB, Bl 4KB per buffer
#define A_AL 8192
#define A_BH 16384
#define A_BL 20480
#define GBUFSZ 24576
#define GSM_BYTES (2*GBUFSZ)

// fused attention tiling
#define KSTR 36
#define TILEW (64*KSTR)
#define TILEWB (TILEW*4)
#define SMEM_FUSED (8*TILEW*4)

// weight packing (words of bf16x2 per layer)
#define LW 2097152
#define OFF_SQKV 0
#define OFF_SWO  393216
#define OFF_CQKV 524288
#define OFF_CKV  655360
#define OFF_CWO  917504
#define OFF_FC1  1048576
#define OFF_FC2  1572864

// ---------------- scratch (device globals; no allocs allowed) ----------------
__device__ float g_x[MR*CC];
__device__ float g_tmp[MR*CC];
__device__ float g_qkv[MR*3*CC];
__device__ float g_kv[MR*2*CC];
__device__ float g_ah[BHH*TT*HDD];
__device__ float g_colsum[BHH*HDD];
__device__ unsigned g_enc_mm[2];

__device__ unsigned g_wh[4*LW], g_wl[4*LW];
__device__ unsigned g_xh[MR*CC/2], g_xl[MR*CC/2];
__device__ unsigned g_ench[MR*CC/2], g_encl[MR*CC/2];
__device__ unsigned g_hh[MR*FF/2], g_hl[MR*FF/2];
__device__ unsigned g_aoh[MR*CC/2], g_aol[MR*CC/2];
__device__ unsigned g_qhh[BHH*TT*HDD/2], g_qhl[BHH*TT*HDD/2];
__device__ unsigned g_khh[BHH*TT*HDD/2], g_khl[BHH*TT*HDD/2];
__device__ unsigned g_vth[BHH*HDD*TT/2], g_vtl[BHH*HDD*TT/2];

// ---------------- helpers ----------------
__device__ __forceinline__ unsigned fenc(float x) {
    unsigned u = __float_as_uint(x);
    return (u & 0x80000000u) ? ~u : (u | 0x80000000u);
}
__device__ __forceinline__ float fdec(unsigned e) {
    unsigned u = (e & 0x80000000u) ? (e & 0x7FFFFFFFu) : ~e;
    return __uint_as_float(u);
}
__device__ __forceinline__ void split2(float x0, float x1, unsigned &h, unsigned &l) {
    __nv_bfloat162 hb = __floats2bfloat162_rn(x0, x1);
    float r0 = x0 - __bfloat162float(hb.x);
    float r1 = x1 - __bfloat162float(hb.y);
    __nv_bfloat162 lb = __floats2bfloat162_rn(r0, r1);
    h = *reinterpret_cast<unsigned*>(&hb);
    l = *reinterpret_cast<unsigned*>(&lb);
}
__device__ __forceinline__ float2 b2f(unsigned u) {
    __nv_bfloat162 b = *reinterpret_cast<__nv_bfloat162*>(&u);
    return make_float2(__bfloat162float(b.x), __bfloat162float(b.y));
}
__device__ __forceinline__ void mma_bf16(float (&d)[4], const unsigned (&a)[4], const unsigned (&b)[2]) {
    asm volatile("mma.sync.aligned.m16n8k16.row.col.f32.bf16.bf16.f32 "
        "{%0,%1,%2,%3},{%4,%5,%6,%7},{%8,%9},{%0,%1,%2,%3};\n"
        : "+f"(d[0]), "+f"(d[1]), "+f"(d[2]), "+f"(d[3])
        : "r"(a[0]), "r"(a[1]), "r"(a[2]), "r"(a[3]), "r"(b[0]), "r"(b[1]));
}
__device__ __forceinline__ uint32_t smem_to_u32(const void* p) {
    uint32_t a;
    asm("{ .reg .u64 t; cvta.to.shared.u64 t, %1; cvt.u32.u64 %0, t; }" : "=r"(a) : "l"(p));
    return a;
}
__device__ __forceinline__ void ldsm_x4(unsigned &r0, unsigned &r1, unsigned &r2, unsigned &r3,
                                        uint32_t addr) {
    asm volatile("ldmatrix.sync.aligned.m8n8.x4.shared.b16 {%0,%1,%2,%3}, [%4];"
        : "=r"(r0), "=r"(r1), "=r"(r2), "=r"(r3) : "r"(addr));
}
#define CP_ASYNC16(dst, src) \
    asm volatile("cp.async.cg.shared.global [%0], [%1], 16;\n" :: "r"(dst), "l"(src))
#define CP_COMMIT() asm volatile("cp.async.commit_group;\n" ::: "memory")
#define CP_WAIT0()  asm volatile("cp.async.wait_group 0;\n" ::: "memory")
#define CP_WAIT1()  asm volatile("cp.async.wait_group 1;\n" ::: "memory")

// swizzled byte offset of (logical row R, 16B chunk q) inside one array
__device__ __forceinline__ uint32_t swz(int row, int q) {
    return (uint32_t)((row >> 1) * 128 + ((((row & 1) << 2) | q) ^ ((row >> 1) & 7)) * 16);
}

// ---------------- weight pre-split (once per launch) ----------------
__global__ void __launch_bounds__(256) conv_weights(
    const float* __restrict__ sW, const float* __restrict__ sWo,
    const float* __restrict__ cW, const float* __restrict__ cWo,
    const float* __restrict__ f1, const float* __restrict__ f2)
{
    int l = blockIdx.y;
    int w = blockIdx.x * 256 + threadIdx.x;
    const float* src; int wl;
    if      (w < 393216)  { src = sW  + (size_t)l*786432;  wl = w; }
    else if (w < 524288)  { src = sWo + (size_t)l*262144;  wl = w - 393216; }
    else if (w < 917504)  { src = cW  + (size_t)l*786432;  wl = w - 524288; }
    else if (w < 1048576) { src = cWo + (size_t)l*262144;  wl = w - 917504; }
    else if (w < 1572864) { src = f1  + (size_t)l*1048576; wl = w - 1048576; }
    else                  { src = f2  + (size_t)l*1048576; wl = w - 1572864; }
    float2 v = *(const float2*)(src + 2*(size_t)wl);
    unsigned h, lo;
    split2(v.x, v.y, h, lo);
    g_wh[(size_t)l*LW + w] = h;
    g_wl[(size_t)l*LW + w] = lo;
}

__global__ void __launch_bounds__(256) split_f32(
    const float* __restrict__ src, unsigned* __restrict__ dh, unsigned* __restrict__ dl)
{
    int idx = blockIdx.x * 256 + threadIdx.x;
    float2 v = *(const float2*)(src + 2*(size_t)idx);
    split2(v.x, v.y, dh[idx], dl[idx]);
}

// ---------------- positional embedding + input add ----------------
__global__ void __launch_bounds__(256) pos_embed_kernel(
    const float* __restrict__ xin, const int* __restrict__ tokens)
{
    int idx = blockIdx.x * 256 + threadIdx.x;
    if (idx >= MR*CC/2) return;
    int cw = idx & 255;
    int r = idx >> 8;
    int b = r & 1;
    int t = r >> 1;
    int c = 2*cw;
    float x0 = xin[(size_t)r*CC + c], x1 = xin[(size_t)r*CC + c + 1];
    if (tokens[b*TT + t] != 0) {
        int j0 = (c < 256) ? c : c - 256;
        float f0 = expf((float)j0 * (-9.210340371976184f / 255.0f));
        float f1 = expf((float)(j0+1) * (-9.210340371976184f / 255.0f));
        float a0 = (float)(t + 1) * f0, a1 = (float)(t + 1) * f1;
        x0 += (c < 256) ? sinf(a0) : cosf(a0);
        x1 += (c < 256) ? sinf(a1) : cosf(a1);
    }
    g_x[(size_t)r*CC + c] = x0;
    g_x[(size_t)r*CC + c + 1] = x1;
    split2(x0, x1, g_xh[idx], g_xl[idx]);
}

// ================= bf16 hi/lo TN GEMM, 128x64 tile, swizzled smem, 3 CTAs/SM =================
template<bool RELU, bool SPLIT>
__global__ void __launch_bounds__(256, 3) gemm_bf16s(
    const unsigned* __restrict__ Agh, const unsigned* __restrict__ Agl,
    const unsigned* __restrict__ Wgh, const unsigned* __restrict__ Wgl,
    const float* __restrict__ bias, float* __restrict__ out,
    unsigned* __restrict__ outh, unsigned* __restrict__ outl,
    int N, int K)
{
    extern __shared__ unsigned gsm[];
    const uint32_t sb = smem_to_u32(gsm);
    const int tid = threadIdx.x;
    const int m0 = blockIdx.y * BM, n0 = blockIdx.x * GBN;
    const int K2 = K >> 1;

    const unsigned* bases[4] = {
        Agh + (size_t)m0 * K2, Agl + (size_t)m0 * K2,
        Wgh + (size_t)n0 * K2, Wgl + (size_t)n0 * K2 };
    const uint32_t arrOff[4] = { 0u, A_AL, A_BH, A_BL };

    auto stage = [&](int kt, int buf) {
        uint32_t dst0 = sb + buf * GBUFSZ;
        #pragma unroll
        for (int i = 0; i < 6; i++) {
            int c = i * 256 + tid;
            int arr, u;
            if (i < 2)       { arr = 0; u = c; }
            else if (i < 4)  { arr = 1; u = c - 512; }
            else if (i == 4) { arr = 2; u = c - 1024; }
            else             { arr = 3; u = c - 1280; }
            int row = u >> 2, q = u & 3;
            const unsigned* src = bases[arr] + (size_t)row * K2 + kt * 16 + q * 4;
            uint32_t dst = dst0 + arrOff[arr] + swz(row, q);
            CP_ASYNC16(dst, src);
        }
        CP_COMMIT();
    };

    const int wid = tid >> 5, lane = tid & 31;
    const int wy = wid >> 1, wx = wid & 1;     // 4 x 2 warps, 32x32 each
    const int lq = lane >> 2, lr = lane & 3;
    const int wm = wy * 32, wn = wx * 32;

    // ldmatrix per-lane constants
    const int row_offA = ((lane >> 3) & 1) * 8 + (lane & 7);
    const int hia = (lane >> 4) & 1;
    const int r2a = row_offA >> 1, halfa = row_offA & 1;
    const uint32_t aRow = (uint32_t)(wm * 64 + r2a * 128);
    const uint32_t chA0 = (uint32_t)(((((halfa << 2) | hia)     ) ^ r2a) * 16);
    const uint32_t chA1 = (uint32_t)(((((halfa << 2) | (2 + hia))) ^ r2a) * 16);

    const int row_offB = ((lane >> 4) & 1) * 8 + (lane & 7);
    const int hib = (lane >> 3) & 1;
    const int r2b = row_offB >> 1, halfb = row_offB & 1;
    const uint32_t bRow = (uint32_t)(A_BH + wn * 64 + r2b * 128);
    const uint32_t chB0 = (uint32_t)(((((halfb << 2) | hib)     ) ^ r2b) * 16);
    const uint32_t chB1 = (uint32_t)(((((halfb << 2) | (2 + hib))) ^ r2b) * 16);

    float acc[2][4][4];
    #pragma unroll
    for (int i = 0; i < 2; i++)
        #pragma unroll
        for (int j = 0; j < 4; j++)
            #pragma unroll
            for (int q = 0; q < 4; q++) acc[i][j][q] = 0.f;

    const int KT = K / BK;
    stage(0, 0);

    for (int kt = 0; kt < KT; kt++) {
        const int buf = kt & 1;
        if (kt + 1 < KT) { stage(kt + 1, buf ^ 1); CP_WAIT1(); }
        else             { CP_WAIT0(); }
        __syncthreads();

        const uint32_t bufB = sb + buf * GBUFSZ;
        #pragma unroll
        for (int ks = 0; ks < 2; ks++) {
            const uint32_t cA = ks ? chA1 : chA0;
            const uint32_t cB = ks ? chB1 : chB0;
            unsigned ah[2][4], al_[2][4];
            #pragma unroll
            for (int mt = 0; mt < 2; mt++) {
                uint32_t ad = bufB + aRow + mt * 1024 + cA;
                ldsm_x4(ah[mt][0], ah[mt][1], ah[mt][2], ah[mt][3], ad);
                ldsm_x4(al_[mt][0], al_[mt][1], al_[mt][2], al_[mt][3], ad + A_AL);
            }
            unsigned bh_[4][2], bl_[4][2];
            #pragma unroll
            for (int p = 0; p < 2; p++) {
                uint32_t bd = bufB + bRow + p * 1024 + cB;
                ldsm_x4(bh_[2*p][0], bh_[2*p][1], bh_[2*p+1][0], bh_[2*p+1][1], bd);
                ldsm_x4(bl_[2*p][0], bl_[2*p][1], bl_[2*p+1][0], bl_[2*p+1][1], bd + 4096);
            }
            #pragma unroll
            for (int mt = 0; mt < 2; mt++)
                #pragma unroll
                for (int nt = 0; nt < 4; nt++) {
                    mma_bf16(acc[mt][nt], ah[mt],  bh_[nt]);
                    mma_bf16(acc[mt][nt], ah[mt],  bl_[nt]);
                    mma_bf16(acc[mt][nt], al_[mt], bh_[nt]);
                }
        }
        __syncthreads();
    }

    #pragma unroll
    for (int mt = 0; mt < 2; mt++) {
        int m = m0 + wm + mt*16 + lq;
        #pragma unroll
        for (int nt = 0; nt < 4; nt++) {
            int n = n0 + wn + nt*8 + 2*lr;
            float2 bv = *(const float2*)(bias + n);
            float v0 = acc[mt][nt][0] + bv.x;
            float v1 = acc[mt][nt][1] + bv.y;
            float v2 = acc[mt][nt][2] + bv.x;
            float v3 = acc[mt][nt][3] + bv.y;
            if (RELU) { v0=fmaxf(v0,0.f); v1=fmaxf(v1,0.f); v2=fmaxf(v2,0.f); v3=fmaxf(v3,0.f); }
            if (SPLIT) {
                split2(v0, v1, outh[((size_t)m*N + n) >> 1], outl[((size_t)m*N + n) >> 1]);
                split2(v2, v3, outh[((size_t)(m+8)*N + n) >> 1], outl[((size_t)(m+8)*N + n) >> 1]);
            } else {
                *(float2*)(out + (size_t)m*N + n)     = make_float2(v0, v1);
                *(float2*)(out + (size_t)(m+8)*N + n) = make_float2(v2, v3);
            }
        }
    }
}

// ================= fused attention: U = (masked scores) @ V, cp.async, 2 CTAs/SM =================
__global__ void __launch_bounds__(256, 2) attn_fused(int causal)
{
    extern __shared__ unsigned sm[];
    __shared__ float rlo[8], rhi[8];
    const uint32_t smb = smem_to_u32(sm);

    const int bh = blockIdx.y;
    const int t0 = (gridDim.x - 1 - blockIdx.x) * 128;
    const int tid = threadIdx.x;
    const int wid = tid >> 5, lane = tid & 31;
    const int lq = lane >> 2, lr = lane & 3;
    const int trow = t0 + wid*16 + lq;

    // ldmatrix per-lane base (B-type fragments for K and V)
    const int row_offB = ((lane >> 4) & 1) * 8 + (lane & 7);
    const int word_offB = ((lane >> 3) & 1) * 4;
    const uint32_t fragBase = smb + (row_offB * KSTR + word_offB) * 4;

    unsigned qah[4][4], qal[4][4];
    {
        const size_t base = ((size_t)bh*TT + trow) * 32;
        #pragma unroll
        for (int ks = 0; ks < 4; ks++) {
            int o = ks*8 + lr;
            qah[ks][0] = g_qhh[base + o];        qal[ks][0] = g_qhl[base + o];
            qah[ks][1] = g_qhh[base + 256 + o];  qal[ks][1] = g_qhl[base + 256 + o];
            qah[ks][2] = g_qhh[base + o + 4];    qal[ks][2] = g_qhl[base + o + 4];
            qah[ks][3] = g_qhh[base + 256 + o + 4]; qal[ks][3] = g_qhl[base + 256 + o + 4];
        }
    }

    float uacc[8][4];
    #pragma unroll
    for (int i = 0; i < 8; i++)
        #pragma unroll
        for (int q = 0; q < 4; q++) uacc[i][q] = 0.f;

    float lo = 3.4e38f, hi = -3.4e38f;
    const int nst = causal ? (t0/64 + 2) : (TT/64);

    // cp.async staging: 64 rows x 4 threads/row, 8 words (2x16B) each, 4 arrays
    const int prow = tid >> 2;
    const int pw = (tid & 3) * 8;
    const uint32_t wbyte0 = (uint32_t)(prow*KSTR + pw) * 4;
    const unsigned* kpb  = g_khh + ((size_t)bh*TT + prow)*32 + pw;
    const unsigned* klpb = g_khl + ((size_t)bh*TT + prow)*32 + pw;
    const unsigned* vpb  = g_vth + ((size_t)bh*HDD + prow)*(TT/2) + pw;
    const unsigned* vlpb = g_vtl + ((size_t)bh*HDD + prow)*(TT/2) + pw;

    auto stageA = [&](int st, int buf) {
        int sn = st * 64;
        uint32_t d0 = smb + buf * TILEWB + wbyte0;
        const unsigned* kp  = kpb  + (size_t)sn * 32;
        const unsigned* klp = klpb + (size_t)sn * 32;
        const unsigned* vp  = vpb  + sn/2;
        const unsigned* vlp = vlpb + sn/2;
        CP_ASYNC16(d0,              kp);      CP_ASYNC16(d0 + 16,              kp + 4);
        CP_ASYNC16(d0 + 2*TILEWB,   klp);     CP_ASYNC16(d0 + 2*TILEWB + 16,   klp + 4);
        CP_ASYNC16(d0 + 4*TILEWB,   vp);      CP_ASYNC16(d0 + 4*TILEWB + 16,   vp + 4);
        CP_ASYNC16(d0 + 6*TILEWB,   vlp);     CP_ASYNC16(d0 + 6*TILEWB + 16,   vlp + 4);
        CP_COMMIT();
    };

    stageA(0, 0);

    for (int st = 0; st < nst; st++) {
        const int buf = st & 1;
        if (st + 1 < nst) { stageA(st + 1, buf ^ 1); CP_WAIT1(); }
        else              { CP_WAIT0(); }
        __syncthreads();

        const uint32_t bufB = buf * TILEWB;
        const int s0 = st * 64;

        float sacc[8][4];
        #pragma unroll
        for (int i = 0; i < 8; i++)
            #pragma unroll
            for (int q = 0; q < 4; q++) sacc[i][q] = 0.f;

        // ---- S = Q K^T ----
        #pragma unroll
        for (int ks = 0; ks < 4; ks++) {
            #pragma unroll
            for (int p = 0; p < 4; p++) {
                uint32_t kd = fragBase + bufB + (p * 16 * KSTR + ks * 8) * 4;
                unsigned bbh[4], bbl[4];
                ldsm_x4(bbh[0], bbh[1], bbh[2], bbh[3], kd);
                ldsm_x4(bbl[0], bbl[1], bbl[2], bbl[3], kd + 2*TILEWB);
                unsigned h0[2] = { bbh[0], bbh[1] }, h1[2] = { bbh[2], bbh[3] };
                unsigned l0[2] = { bbl[0], bbl[1] }, l1[2] = { bbl[2], bbl[3] };
                mma_bf16(sacc[2*p],   qah[ks], h0);
                mma_bf16(sacc[2*p],   qal[ks], h0);
                mma_bf16(sacc[2*p],   qah[ks], l0);
                mma_bf16(sacc[2*p+1], qah[ks], h1);
                mma_bf16(sacc[2*p+1], qal[ks], h1);
                mma_bf16(sacc[2*p+1], qah[ks], l1);
            }
        }

        if (causal) {
            #pragma unroll
            for (int nt = 0; nt < 8; nt++) {
                int sg = s0 + nt*8 + 2*lr;
                if (sg     > trow)     sacc[nt][0] = 0.f;
                if (sg + 1 > trow)     sacc[nt][1] = 0.f;
                if (sg     > trow + 8) sacc[nt][2] = 0.f;
                if (sg + 1 > trow + 8) sacc[nt][3] = 0.f;
            }
        }
        #pragma unroll
        for (int nt = 0; nt < 8; nt++) {
            lo = fminf(lo, fminf(fminf(sacc[nt][0], sacc[nt][1]), fminf(sacc[nt][2], sacc[nt][3])));
            hi = fmaxf(hi, fmaxf(fmaxf(sacc[nt][0], sacc[nt][1]), fmaxf(sacc[nt][2], sacc[nt][3])));
        }

        // ---- U += S @ V ----
        #pragma unroll
        for (int ks = 0; ks < 4; ks++) {
            unsigned sah[4], sal[4];
            split2(sacc[2*ks  ][0], sacc[2*ks  ][1], sah[0], sal[0]);
            split2(sacc[2*ks  ][2], sacc[2*ks  ][3], sah[1], sal[1]);
            split2(sacc[2*ks+1][0], sacc[2*ks+1][1], sah[2], sal[2]);
            split2(sacc[2*ks+1][2], sacc[2*ks+1][3], sah[3], sal[3]);
            #pragma unroll
            for (int p = 0; p < 4; p++) {
                uint32_t vd = fragBase + bufB + 4*TILEWB + (p * 16 * KSTR + ks * 8) * 4;
                unsigned vvh[4], vvl[4];
                ldsm_x4(vvh[0], vvh[1], vvh[2], vvh[3], vd);
                ldsm_x4(vvl[0], vvl[1], vvl[2], vvl[3], vd + 2*TILEWB);
                unsigned h0[2] = { vvh[0], vvh[1] }, h1[2] = { vvh[2], vvh[3] };
                unsigned l0[2] = { vvl[0], vvl[1] }, l1[2] = { vvl[2], vvl[3] };
                mma_bf16(uacc[2*p],   sah, h0);
                mma_bf16(uacc[2*p],   sal, h0);
                mma_bf16(uacc[2*p],   sah, l0);
                mma_bf16(uacc[2*p+1], sah, h1);
                mma_bf16(uacc[2*p+1], sal, h1);
                mma_bf16(uacc[2*p+1], sah, l1);
            }
        }
        __syncthreads();   // all warps done with buf before next stage overwrites
    }

    #pragma unroll
    for (int dt = 0; dt < 8; dt++) {
        int n = dt*8 + 2*lr;
        *(float2*)(g_ah + ((size_t)bh*TT + trow)*HDD + n)     = make_float2(uacc[dt][0], uacc[dt][1]);
        *(float2*)(g_ah + ((size_t)bh*TT + trow + 8)*HDD + n) = make_float2(uacc[dt][2], uacc[dt][3]);
    }

    #pragma unroll
    for (int o = 16; o > 0; o >>= 1) {
        lo = fminf(lo, __shfl_xor_sync(0xFFFFFFFFu, lo, o));
        hi = fmaxf(hi, __shfl_xor_sync(0xFFFFFFFFu, hi, o));
    }
    if (lane == 0) { rlo[wid] = lo; rhi[wid] = hi; }
    __syncthreads();
    if (tid == 0) {
        float l2 = rlo[0], h2 = rhi[0];
        #pragma unroll
        for (int w = 1; w < 8; w++) { l2 = fminf(l2, rlo[w]); h2 = fmaxf(h2, rhi[w]); }
        atomicMin(&g_enc_mm[0], fenc(l2));
        atomicMax(&g_enc_mm[1], fenc(h2));
    }
}

// ---------------- split heads (q,k) -> packed hi/lo [bh][t][d] ----------------
__global__ void __launch_bounds__(256) split_heads_qk(
    const float* __restrict__ qsrc, int qld,
    const float* __restrict__ ksrc, int kld)
{
    int idx = blockIdx.x * 256 + threadIdx.x;
    if (idx >= BHH*TT*32) return;
    int dw = idx & 31;
    int t  = (idx >> 5) & (TT-1);
    int bh = idx >> 16;
    int b = bh >> 3, h = bh & 7;
    size_t r = (size_t)t * BB + b;
    int c = h * HDD + 2*dw;
    float q0 = qsrc[r*qld + c] * 0.125f;
    float q1 = qsrc[r*qld + c + 1] * 0.125f;
    split2(q0, q1, g_qhh[idx], g_qhl[idx]);
    float k0 = ksrc[r*kld + c];
    float k1 = ksrc[r*kld + c + 1];
    split2(k0, k1, g_khh[idx], g_khl[idx]);
}

// ---------------- transpose V -> packed hi/lo [bh][d][t] ----------------
__global__ void __launch_bounds__(256) transpose_v(
    const float* __restrict__ vsrc, int ldv)
{
    __shared__ float tile[32][33];
    const int bh = blockIdx.z;
    const int b = bh >> 3, h = bh & 7;
    const int t0 = blockIdx.x * 32, d0 = blockIdx.y * 32;
    const int tx = threadIdx.x & 31, ty = threadIdx.x >> 5;
    #pragma unroll
    for (int j = ty; j < 32; j += 8)
        tile[j][tx] = vsrc[(size_t)((t0 + j)*BB + b) * ldv + h*HDD + d0 + tx];
    __syncthreads();
    int d = threadIdx.x >> 3;
    int twl = threadIdx.x & 7;
    #pragma unroll
    for (int rep = 0; rep < 2; rep++) {
        int tw = twl + rep*8;
        float v0 = tile[2*tw][d], v1 = tile[2*tw+1][d];
        size_t o = ((size_t)bh*HDD + d0 + d) * (TT/2) + (t0 >> 1) + tw;
        split2(v0, v1, g_vth[o], g_vtl[o]);
    }
}

// ---------------- column sums of V per (bh,d) + min/max reset (fused) ----------------
__global__ void __launch_bounds__(256) colsum_v(int causal)
{
    if (blockIdx.x == 0 && threadIdx.x == 0) {
        unsigned z = fenc(0.f);
        g_enc_mm[0] = causal ? z : 0xFFFFFFFFu;
        g_enc_mm[1] = causal ? z : 0u;
    }
    const int bh = blockIdx.x >> 3;
    const int wid = threadIdx.x >> 5, lane = threadIdx.x & 31;
    const int d = (blockIdx.x & 7) * 8 + wid;
    const uint4* ph = (const uint4*)(g_vth + ((size_t)bh*HDD + d) * (TT/2));
    const uint4* pl = (const uint4*)(g_vtl + ((size_t)bh*HDD + d) * (TT/2));
    float s = 0.f;
    #pragma unroll
    for (int i = lane; i < TT/8; i += 32) {
        uint4 h4 = ph[i], l4 = pl[i];
        float2 a = b2f(h4.x), bq = b2f(h4.y), c = b2f(h4.z), dd = b2f(h4.w);
        float2 e = b2f(l4.x), f = b2f(l4.y), g = b2f(l4.z), hh2 = b2f(l4.w);
        s += a.x+a.y + bq.x+bq.y + c.x+c.y + dd.x+dd.y
           + e.x+e.y + f.x+f.y + g.x+g.y + hh2.x+hh2.y;
    }
    #pragma unroll
    for (int o = 16; o > 0; o >>= 1) s += __shfl_xor_sync(0xFFFFFFFFu, s, o);
    if (lane == 0) g_colsum[bh*HDD + d] = s;
}

// ---------------- merge heads + normalization epilogue -> packed hi/lo ----------------
__global__ void __launch_bounds__(256) merge_heads()
{
    int idx = blockIdx.x * 256 + threadIdx.x;
    if (idx >= MR*CC/2) return;
    float mn = fdec(g_enc_mm[0]);
    float inv = 1.0f / (fdec(g_enc_mm[1]) - mn);
    float k2 = mn * inv;
    int cw = idx & 255;
    int r = idx >> 8;
    int b = r & 1;
    int t = r >> 1;
    int c = 2*cw;
    int h = c >> 6, d = c & 63;
    int bh = b*HH + h;
    float cs0 = g_colsum[bh*HDD + d], cs1 = g_colsum[bh*HDD + d + 1];
    float u0 = g_ah[((size_t)bh*TT + t)*HDD + d];
    float u1 = g_ah[((size_t)bh*TT + t)*HDD + d + 1];
    split2(inv*u0 - k2*cs0, inv*u1 - k2*cs1, g_aoh[idx], g_aol[idx]);
}

// ---------------- residual add + LayerNorm (fp32 + hi/lo out) ----------------
__global__ void __launch_bounds__(128) add_ln(
    float* __restrict__ x, const float* __restrict__ dlt,
    const float* __restrict__ g, const float* __restrict__ b)
{
    const int r = blockIdx.x;
    const int tid = threadIdx.x;
    __shared__ float sred[128];
    float4 xv = *(float4*)(x + (size_t)r*CC + tid*4);
    float4 dv = *(const float4*)(dlt + (size_t)r*CC + tid*4);
    float y0 = xv.x+dv.x, y1 = xv.y+dv.y, y2 = xv.z+dv.z, y3 = xv.w+dv.w;

    sred[tid] = y0+y1+y2+y3;
    __syncthreads();
    for (int s = 64; s > 0; s >>= 1) {
        if (tid < s) sred[tid] += sred[tid+s];
        __syncthreads();
    }
    float mu = sred[0] * (1.0f/CC);
    __syncthreads();

    float d0 = y0-mu, d1 = y1-mu, d2 = y2-mu, d3 = y3-mu;
    sred[tid] = d0*d0 + d1*d1 + d2*d2 + d3*d3;
    __syncthreads();
    for (int s = 64; s > 0; s >>= 1) {
        if (tid < s) sred[tid] += sred[tid+s];
        __syncthreads();
    }
    float rstd = rsqrtf(sred[0] * (1.0f/CC) + 1e-20f);

    float4 gv = *(const float4*)(g + tid*4);
    float4 bv = *(const float4*)(b + tid*4);
    float4 ov;
    ov.x = d0*rstd*gv.x + bv.x;
    ov.y = d1*rstd*gv.y + bv.y;
    ov.z = d2*rstd*gv.z + bv.z;
    ov.w = d3*rstd*gv.w + bv.w;
    *(float4*)(x + (size_t)r*CC + tid*4) = ov;
    int widx = r*256 + tid*2;
    split2(ov.x, ov.y, g_xh[widx], g_xl[widx]);
    split2(ov.z, ov.w, g_xh[widx+1], g_xl[widx+1]);
}

__global__ void __launch_bounds__(256) copy_out(float* __restrict__ out)
{
    int idx = blockIdx.x * 256 + threadIdx.x;
    if (idx < MR*CC) out[idx] = g_x[idx];
}

// ---------------- host orchestration ----------------
extern "C" void kernel_launch(void* const* d_in, const int* in_sizes, int n_in,
                              void* d_out, int out_size)
{
    const float* x       = (const float*)d_in[0];
    const float* enc     = (const float*)d_in[1];
    const int*   tokens  = (const int*)  d_in[2];
    const float* sWqkv   = (const float*)d_in[3];
    const float* sbqkv   = (const float*)d_in[4];
    const float* sWo     = (const float*)d_in[5];
    const float* sbo     = (const float*)d_in[6];
    const float* cWqkv   = (const float*)d_in[7];
    const float* cbqkv   = (const float*)d_in[8];
    const float* cWo     = (const float*)d_in[9];
    const float* cbo     = (const float*)d_in[10];
    const float* fc1w    = (const float*)d_in[11];
    const float* fc1b    = (const float*)d_in[12];
    const float* fc2w    = (const float*)d_in[13];
    const float* fc2b    = (const float*)d_in[14];
    const float* ln1g    = (const float*)d_in[15];
    const float* ln1b    = (const float*)d_in[16];
    const float* ln2g    = (const float*)d_in[17];
    const float* ln2b    = (const float*)d_in[18];
    const float* ln3g    = (const float*)d_in[19];
    const float* ln3b    = (const float*)d_in[20];

    static int attr_set = 0;
    if (!attr_set) {
        cudaFuncSetAttribute(attn_fused, cudaFuncAttributeMaxDynamicSharedMemorySize, SMEM_FUSED);
        cudaFuncSetAttribute(gemm_bf16s<false,false>, cudaFuncAttributeMaxDynamicSharedMemorySize, GSM_BYTES);
        cudaFuncSetAttribute(gemm_bf16s<true,true>,  cudaFuncAttributeMaxDynamicSharedMemorySize, GSM_BYTES);
        attr_set = 1;
    }

    float *px, *ptmp, *pqkv, *pkv;
    cudaGetSymbolAddress((void**)&px,   g_x);
    cudaGetSymbolAddress((void**)&ptmp, g_tmp);
    cudaGetSymbolAddress((void**)&pqkv, g_qkv);
    cudaGetSymbolAddress((void**)&pkv,  g_kv);
    unsigned *pwh, *pwl, *pxh, *pxl, *pench, *pencl, *phh, *phl, *paoh, *paol;
    cudaGetSymbolAddress((void**)&pwh, g_wh);
    cudaGetSymbolAddress((void**)&pwl, g_wl);
    cudaGetSymbolAddress((void**)&pxh, g_xh);
    cudaGetSymbolAddress((void**)&pxl, g_xl);
    cudaGetSymbolAddress((void**)&pench, g_ench);
    cudaGetSymbolAddress((void**)&pencl, g_encl);
    cudaGetSymbolAddress((void**)&phh, g_hh);
    cudaGetSymbolAddress((void**)&phl, g_hl);
    cudaGetSymbolAddress((void**)&paoh, g_aoh);
    cudaGetSymbolAddress((void**)&paol, g_aol);

    conv_weights<<<dim3(LW/256, NLAYER), 256>>>(sWqkv, sWo, cWqkv, cWo, fc1w, fc2w);
    split_f32<<<MR*CC/2/256, 256>>>(enc, pench, pencl);
    pos_embed_kernel<<<MR*CC/2/256, 256>>>(x, tokens);

    for (int l = 0; l < NLAYER; l++) {
        const unsigned* lwh = pwh + (size_t)l*LW;
        const unsigned* lwl = pwl + (size_t)l*LW;

        // ---- self-attention ----
        gemm_bf16s<false,false><<<dim3(3*CC/GBN, MR/BM), 256, GSM_BYTES>>>(
            pxh, pxl, lwh + OFF_SQKV, lwl + OFF_SQKV, sbqkv + (size_t)l*3*CC,
            pqkv, nullptr, nullptr, 3*CC, CC);
        split_heads_qk<<<BHH*TT*32/256, 256>>>(pqkv, 3*CC, pqkv + CC, 3*CC);
        transpose_v<<<dim3(TT/32, HDD/32, BHH), 256>>>(pqkv + 2*CC, 3*CC);
        colsum_v<<<BHH*8, 256>>>(1);
        attn_fused<<<dim3(TT/128, BHH), 256, SMEM_FUSED>>>(1);
        merge_heads<<<MR*CC/2/256, 256>>>();
        gemm_bf16s<false,false><<<dim3(CC/GBN, MR/BM), 256, GSM_BYTES>>>(
            paoh, paol, lwh + OFF_SWO, lwl + OFF_SWO, sbo + (size_t)l*CC,
            ptmp, nullptr, nullptr, CC, CC);
        add_ln<<<MR, 128>>>(px, ptmp, ln1g + l*CC, ln1b + l*CC);

        // ---- cross-attention ----
        gemm_bf16s<false,false><<<dim3(CC/GBN, MR/BM), 256, GSM_BYTES>>>(
            pxh, pxl, lwh + OFF_CQKV, lwl + OFF_CQKV, cbqkv + (size_t)l*3*CC,
            pqkv, nullptr, nullptr, CC, CC);
        gemm_bf16s<false,false><<<dim3(2*CC/GBN, MR/BM), 256, GSM_BYTES>>>(
            pench, pencl, lwh + OFF_CKV, lwl + OFF_CKV, cbqkv + (size_t)l*3*CC + CC,
            pkv, nullptr, nullptr, 2*CC, CC);
        split_heads_qk<<<BHH*TT*32/256, 256>>>(pqkv, CC, pkv, 2*CC);
        transpose_v<<<dim3(TT/32, HDD/32, BHH), 256>>>(pkv + CC, 2*CC);
        colsum_v<<<BHH*8, 256>>>(0);
        attn_fused<<<dim3(TT/128, BHH), 256, SMEM_FUSED>>>(0);
        merge_heads<<<MR*CC/2/256, 256>>>();
        gemm_bf16s<false,false><<<dim3(CC/GBN, MR/BM), 256, GSM_BYTES>>>(
            paoh, paol, lwh + OFF_CWO, lwl + OFF_CWO, cbo + (size_t)l*CC,
            ptmp, nullptr, nullptr, CC, CC);
        add_ln<<<MR, 128>>>(px, ptmp, ln2g + l*CC, ln2b + l*CC);

        // ---- FFN ----
        gemm_bf16s<true,true><<<dim3(FF/GBN, MR/BM), 256, GSM_BYTES>>>(
            pxh, pxl, lwh + OFF_FC1, lwl + OFF_FC1, fc1b + (size_t)l*FF,
            nullptr, phh, phl, FF, CC);
        gemm_bf16s<false,false><<<dim3(CC/GBN, MR/BM), 256, GSM_BYTES>>>(
            phh, phl, lwh + OFF_FC2, lwl + OFF_FC2, fc2b + (size_t)l*CC,
            ptmp, nullptr, nullptr, CC, FF);
        add_ln<<<MR, 128>>>(px, ptmp, ln3g + l*CC, ln3b + l*CC);
    }

    copy_out<<<MR*CC/256, 256>>>((float*)d_out);
}

// round 14
// speedup vs baseline: 1.0019x; 1.0019x over previous
#include <cuda_runtime.h>
#include <cuda_bf16.h>
#include <math.h>
#include <stdint.h>
#include <stddef.h>

// Problem dims (fixed)
#define TT 2048
#define BB 2
#define CC 512
#define HH 8
#define HDD 64
#define FF 2048
#define NLAYER 4
#define MR (TT*BB)
#define BHH (BB*HH)

#define BM 128
#define GBN 64
#define BK 32

// GEMM smem (swizzled, no padding): Ah 8KB, Al 8KB, Bh 4KB, Bl 4KB per buffer, 3 stages
#define A_AL 8192
#define A_BH 16384
#define A_BL 20480
#define GBUFSZ 24576
#define GSM_BYTES (3*GBUFSZ)

// fused attention tiling
#define KSTR 36
#define TILEW (64*KSTR)
#define TILEWB (TILEW*4)
#define SMEM_FUSED (8*TILEW*4)

// weight packing (words of bf16x2 per layer)
#define LW 2097152
#define OFF_SQKV 0
#define OFF_SWO  393216
#define OFF_CQKV 524288
#define OFF_CKV  655360
#define OFF_CWO  917504
#define OFF_FC1  1048576
#define OFF_FC2  1572864

// ---------------- scratch (device globals; no allocs allowed) ----------------
__device__ float g_x[MR*CC];
__device__ float g_tmp[MR*CC];
__device__ float g_qkv[MR*3*CC];
__device__ float g_kv[MR*2*CC];
__device__ float g_ah[BHH*TT*HDD];
__device__ float g_colsum[BHH*HDD];
__device__ unsigned g_enc_mm[2];

__device__ unsigned g_wh[4*LW], g_wl[4*LW];
__device__ unsigned g_xh[MR*CC/2], g_xl[MR*CC/2];
__device__ unsigned g_ench[MR*CC/2], g_encl[MR*CC/2];
__device__ unsigned g_hh[MR*FF/2], g_hl[MR*FF/2];
__device__ unsigned g_aoh[MR*CC/2], g_aol[MR*CC/2];
__device__ unsigned g_qhh[BHH*TT*HDD/2], g_qhl[BHH*TT*HDD/2];
__device__ unsigned g_khh[BHH*TT*HDD/2], g_khl[BHH*TT*HDD/2];
__device__ unsigned g_vth[BHH*HDD*TT/2], g_vtl[BHH*HDD*TT/2];

// ---------------- helpers ----------------
__device__ __forceinline__ unsigned fenc(float x) {
    unsigned u = __float_as_uint(x);
    return (u & 0x80000000u) ? ~u : (u | 0x80000000u);
}
__device__ __forceinline__ float fdec(unsigned e) {
    unsigned u = (e & 0x80000000u) ? (e & 0x7FFFFFFFu) : ~e;
    return __uint_as_float(u);
}
__device__ __forceinline__ void split2(float x0, float x1, unsigned &h, unsigned &l) {
    __nv_bfloat162 hb = __floats2bfloat162_rn(x0, x1);
    float r0 = x0 - __bfloat162float(hb.x);
    float r1 = x1 - __bfloat162float(hb.y);
    __nv_bfloat162 lb = __floats2bfloat162_rn(r0, r1);
    h = *reinterpret_cast<unsigned*>(&hb);
    l = *reinterpret_cast<unsigned*>(&lb);
}
__device__ __forceinline__ float2 b2f(unsigned u) {
    __nv_bfloat162 b = *reinterpret_cast<__nv_bfloat162*>(&u);
    return make_float2(__bfloat162float(b.x), __bfloat162float(b.y));
}
__device__ __forceinline__ void mma_bf16(float (&d)[4], const unsigned (&a)[4], const unsigned (&b)[2]) {
    asm volatile("mma.sync.aligned.m16n8k16.row.col.f32.bf16.bf16.f32 "
        "{%0,%1,%2,%3},{%4,%5,%6,%7},{%8,%9},{%0,%1,%2,%3};\n"
        : "+f"(d[0]), "+f"(d[1]), "+f"(d[2]), "+f"(d[3])
        : "r"(a[0]), "r"(a[1]), "r"(a[2]), "r"(a[3]), "r"(b[0]), "r"(b[1]));
}
__device__ __forceinline__ uint32_t smem_to_u32(const void* p) {
    uint32_t a;
    asm("{ .reg .u64 t; cvta.to.shared.u64 t, %1; cvt.u32.u64 %0, t; }" : "=r"(a) : "l"(p));
    return a;
}
__device__ __forceinline__ void ldsm_x4(unsigned &r0, unsigned &r1, unsigned &r2, unsigned &r3,
                                        uint32_t addr) {
    asm volatile("ldmatrix.sync.aligned.m8n8.x4.shared.b16 {%0,%1,%2,%3}, [%4];"
        : "=r"(r0), "=r"(r1), "=r"(r2), "=r"(r3) : "r"(addr));
}
#define CP_ASYNC16(dst, src) \
    asm volatile("cp.async.cg.shared.global [%0], [%1], 16;\n" :: "r"(dst), "l"(src))
#define CP_COMMIT() asm volatile("cp.async.commit_group;\n" ::: "memory")
#define CP_WAIT0()  asm volatile("cp.async.wait_group 0;\n" ::: "memory")
#define CP_WAIT1()  asm volatile("cp.async.wait_group 1;\n" ::: "memory")
#define CP_WAIT2()  asm volatile("cp.async.wait_group 2;\n" ::: "memory")

// swizzled byte offset of (logical row R, 16B chunk q) inside one array
__device__ __forceinline__ uint32_t swz(int row, int q) {
    return (uint32_t)((row >> 1) * 128 + ((((row & 1) << 2) | q) ^ ((row >> 1) & 7)) * 16);
}

// ---------------- weight pre-split (once per launch) ----------------
__global__ void __launch_bounds__(256) conv_weights(
    const float* __restrict__ sW, const float* __restrict__ sWo,
    const float* __restrict__ cW, const float* __restrict__ cWo,
    const float* __restrict__ f1, const float* __restrict__ f2)
{
    int l = blockIdx.y;
    int w = blockIdx.x * 256 + threadIdx.x;
    const float* src; int wl;
    if      (w < 393216)  { src = sW  + (size_t)l*786432;  wl = w; }
    else if (w < 524288)  { src = sWo + (size_t)l*262144;  wl = w - 393216; }
    else if (w < 917504)  { src = cW  + (size_t)l*786432;  wl = w - 524288; }
    else if (w < 1048576) { src = cWo + (size_t)l*262144;  wl = w - 917504; }
    else if (w < 1572864) { src = f1  + (size_t)l*1048576; wl = w - 1048576; }
    else                  { src = f2  + (size_t)l*1048576; wl = w - 1572864; }
    float2 v = *(const float2*)(src + 2*(size_t)wl);
    unsigned h, lo;
    split2(v.x, v.y, h, lo);
    g_wh[(size_t)l*LW + w] = h;
    g_wl[(size_t)l*LW + w] = lo;
}

__global__ void __launch_bounds__(256) split_f32(
    const float* __restrict__ src, unsigned* __restrict__ dh, unsigned* __restrict__ dl)
{
    int idx = blockIdx.x * 256 + threadIdx.x;
    float2 v = *(const float2*)(src + 2*(size_t)idx);
    split2(v.x, v.y, dh[idx], dl[idx]);
}

// ---------------- positional embedding + input add ----------------
__global__ void __launch_bounds__(256) pos_embed_kernel(
    const float* __restrict__ xin, const int* __restrict__ tokens)
{
    int idx = blockIdx.x * 256 + threadIdx.x;
    if (idx >= MR*CC/2) return;
    int cw = idx & 255;
    int r = idx >> 8;
    int b = r & 1;
    int t = r >> 1;
    int c = 2*cw;
    float x0 = xin[(size_t)r*CC + c], x1 = xin[(size_t)r*CC + c + 1];
    if (tokens[b*TT + t] != 0) {
        int j0 = (c < 256) ? c : c - 256;
        float f0 = expf((float)j0 * (-9.210340371976184f / 255.0f));
        float f1 = expf((float)(j0+1) * (-9.210340371976184f / 255.0f));
        float a0 = (float)(t + 1) * f0, a1 = (float)(t + 1) * f1;
        x0 += (c < 256) ? sinf(a0) : cosf(a0);
        x1 += (c < 256) ? sinf(a1) : cosf(a1);
    }
    g_x[(size_t)r*CC + c] = x0;
    g_x[(size_t)r*CC + c + 1] = x1;
    split2(x0, x1, g_xh[idx], g_xl[idx]);
}

// ================= bf16 hi/lo TN GEMM, 128x64 tile, swizzled smem, 3-stage, 3 CTAs/SM =================
template<bool RELU, bool SPLIT>
__global__ void __launch_bounds__(256, 3) gemm_bf16s(
    const unsigned* __restrict__ Agh, const unsigned* __restrict__ Agl,
    const unsigned* __restrict__ Wgh, const unsigned* __restrict__ Wgl,
    const float* __restrict__ bias, float* __restrict__ out,
    unsigned* __restrict__ outh, unsigned* __restrict__ outl,
    int N, int K)
{
    extern __shared__ unsigned gsm[];
    const uint32_t sb = smem_to_u32(gsm);
    const int tid = threadIdx.x;
    const int m0 = blockIdx.y * BM, n0 = blockIdx.x * GBN;
    const int K2 = K >> 1;

    const unsigned* bases[4] = {
        Agh + (size_t)m0 * K2, Agl + (size_t)m0 * K2,
        Wgh + (size_t)n0 * K2, Wgl + (size_t)n0 * K2 };
    const uint32_t arrOff[4] = { 0u, A_AL, A_BH, A_BL };

    auto stage = [&](int kt, int buf) {
        uint32_t dst0 = sb + buf * GBUFSZ;
        #pragma unroll
        for (int i = 0; i < 6; i++) {
            int c = i * 256 + tid;
            int arr, u;
            if (i < 2)       { arr = 0; u = c; }
            else if (i < 4)  { arr = 1; u = c - 512; }
            else if (i == 4) { arr = 2; u = c - 1024; }
            else             { arr = 3; u = c - 1280; }
            int row = u >> 2, q = u & 3;
            const unsigned* src = bases[arr] + (size_t)row * K2 + kt * 16 + q * 4;
            uint32_t dst = dst0 + arrOff[arr] + swz(row, q);
            CP_ASYNC16(dst, src);
        }
        CP_COMMIT();
    };

    const int wid = tid >> 5, lane = tid & 31;
    const int wy = wid >> 1, wx = wid & 1;     // 4 x 2 warps, 32x32 each
    const int lq = lane >> 2, lr = lane & 3;
    const int wm = wy * 32, wn = wx * 32;

    // ldmatrix per-lane constants
    const int row_offA = ((lane >> 3) & 1) * 8 + (lane & 7);
    const int hia = (lane >> 4) & 1;
    const int r2a = row_offA >> 1, halfa = row_offA & 1;
    const uint32_t aRow = (uint32_t)(wm * 64 + r2a * 128);
    const uint32_t chA0 = (uint32_t)(((((halfa << 2) | hia)     ) ^ r2a) * 16);
    const uint32_t chA1 = (uint32_t)(((((halfa << 2) | (2 + hia))) ^ r2a) * 16);

    const int row_offB = ((lane >> 4) & 1) * 8 + (lane & 7);
    const int hib = (lane >> 3) & 1;
    const int r2b = row_offB >> 1, halfb = row_offB & 1;
    const uint32_t bRow = (uint32_t)(A_BH + wn * 64 + r2b * 128);
    const uint32_t chB0 = (uint32_t)(((((halfb << 2) | hib)     ) ^ r2b) * 16);
    const uint32_t chB1 = (uint32_t)(((((halfb << 2) | (2 + hib))) ^ r2b) * 16);

    float acc[2][4][4];
    #pragma unroll
    for (int i = 0; i < 2; i++)
        #pragma unroll
        for (int j = 0; j < 4; j++)
            #pragma unroll
            for (int q = 0; q < 4; q++) acc[i][j][q] = 0.f;

    const int KT = K / BK;
    stage(0, 0);
    if (KT > 1) stage(1, 1);

    int buf = 0;
    for (int kt = 0; kt < KT; kt++) {
        // stage kt+2 into its buffer (last computed at kt-1; trailing sync of kt-1 protects it)
        if (kt + 2 < KT) {
            int b2 = buf + 2; if (b2 >= 3) b2 -= 3;
            stage(kt + 2, b2);
            CP_WAIT2();
        } else if (kt + 1 < KT) {
            CP_WAIT1();
        } else {
            CP_WAIT0();
        }
        __syncthreads();

        const uint32_t bufB = sb + buf * GBUFSZ;
        #pragma unroll
        for (int ks = 0; ks < 2; ks++) {
            const uint32_t cA = ks ? chA1 : chA0;
            const uint32_t cB = ks ? chB1 : chB0;
            unsigned ah[2][4], al_[2][4];
            #pragma unroll
            for (int mt = 0; mt < 2; mt++) {
                uint32_t ad = bufB + aRow + mt * 1024 + cA;
                ldsm_x4(ah[mt][0], ah[mt][1], ah[mt][2], ah[mt][3], ad);
                ldsm_x4(al_[mt][0], al_[mt][1], al_[mt][2], al_[mt][3], ad + A_AL);
            }
            unsigned bh_[4][2], bl_[4][2];
            #pragma unroll
            for (int p = 0; p < 2; p++) {
                uint32_t bd = bufB + bRow + p * 1024 + cB;
                ldsm_x4(bh_[2*p][0], bh_[2*p][1], bh_[2*p+1][0], bh_[2*p+1][1], bd);
                ldsm_x4(bl_[2*p][0], bl_[2*p][1], bl_[2*p+1][0], bl_[2*p+1][1], bd + 4096);
            }
            #pragma unroll
            for (int mt = 0; mt < 2; mt++)
                #pragma unroll
                for (int nt = 0; nt < 4; nt++) {
                    mma_bf16(acc[mt][nt], ah[mt],  bh_[nt]);
                    mma_bf16(acc[mt][nt], ah[mt],  bl_[nt]);
                    mma_bf16(acc[mt][nt], al_[mt], bh_[nt]);
                }
        }
        __syncthreads();
        buf = (buf + 1 == 3) ? 0 : buf + 1;
    }

    #pragma unroll
    for (int mt = 0; mt < 2; mt++) {
        int m = m0 + wm + mt*16 + lq;
        #pragma unroll
        for (int nt = 0; nt < 4; nt++) {
            int n = n0 + wn + nt*8 + 2*lr;
            float2 bv = *(const float2*)(bias + n);
            float v0 = acc[mt][nt][0] + bv.x;
            float v1 = acc[mt][nt][1] + bv.y;
            float v2 = acc[mt][nt][2] + bv.x;
            float v3 = acc[mt][nt][3] + bv.y;
            if (RELU) { v0=fmaxf(v0,0.f); v1=fmaxf(v1,0.f); v2=fmaxf(v2,0.f); v3=fmaxf(v3,0.f); }
            if (SPLIT) {
                split2(v0, v1, outh[((size_t)m*N + n) >> 1], outl[((size_t)m*N + n) >> 1]);
                split2(v2, v3, outh[((size_t)(m+8)*N + n) >> 1], outl[((size_t)(m+8)*N + n) >> 1]);
            } else {
                *(float2*)(out + (size_t)m*N + n)     = make_float2(v0, v1);
                *(float2*)(out + (size_t)(m+8)*N + n) = make_float2(v2, v3);
            }
        }
    }
}

// ================= fused attention: U = (masked scores) @ V (R10 version) =================
__global__ void __launch_bounds__(256, 1) attn_fused(int causal)
{
    extern __shared__ unsigned sm[];
    unsigned* Kh = sm;
    unsigned* Kl = sm + 2*TILEW;
    unsigned* Vh = sm + 4*TILEW;
    unsigned* Vl = sm + 6*TILEW;
    __shared__ float rlo[8], rhi[8];
    const uint32_t smb = smem_to_u32(sm);

    const int bh = blockIdx.y;
    const int t0 = (gridDim.x - 1 - blockIdx.x) * 128;
    const int tid = threadIdx.x;
    const int wid = tid >> 5, lane = tid & 31;
    const int lq = lane >> 2, lr = lane & 3;
    const int trow = t0 + wid*16 + lq;

    // ldmatrix per-lane base (B-type fragments for K and V)
    const int row_offB = ((lane >> 4) & 1) * 8 + (lane & 7);
    const int word_offB = ((lane >> 3) & 1) * 4;
    const uint32_t fragBase = smb + (row_offB * KSTR + word_offB) * 4;

    unsigned qah[4][4], qal[4][4];
    {
        const size_t base = ((size_t)bh*TT + trow) * 32;
        #pragma unroll
        for (int ks = 0; ks < 4; ks++) {
            int o = ks*8 + lr;
            qah[ks][0] = g_qhh[base + o];        qal[ks][0] = g_qhl[base + o];
            qah[ks][1] = g_qhh[base + 256 + o];  qal[ks][1] = g_qhl[base + 256 + o];
            qah[ks][2] = g_qhh[base + o + 4];    qal[ks][2] = g_qhl[base + o + 4];
            qah[ks][3] = g_qhh[base + 256 + o + 4]; qal[ks][3] = g_qhl[base + 256 + o + 4];
        }
    }

    float uacc[8][4];
    #pragma unroll
    for (int i = 0; i < 8; i++)
        #pragma unroll
        for (int q = 0; q < 4; q++) uacc[i][q] = 0.f;

    float lo = 3.4e38f, hi = -3.4e38f;
    const int nst = causal ? (t0/64 + 2) : (TT/64);

    const int prow = tid >> 2;
    const int pw = (tid & 3) * 8;
    const int wbase0 = prow*KSTR + pw;

    uint4 kh4[2], kl4[2], vh4[2], vl4[2];
    {
        const unsigned* kp = g_khh + ((size_t)bh*TT + prow)*32 + pw;
        const unsigned* klp = g_khl + ((size_t)bh*TT + prow)*32 + pw;
        const unsigned* vp = g_vth + ((size_t)bh*HDD + prow)*(TT/2) + pw;
        const unsigned* vlp = g_vtl + ((size_t)bh*HDD + prow)*(TT/2) + pw;
        kh4[0]=*(const uint4*)kp;  kh4[1]=*(const uint4*)(kp+4);
        kl4[0]=*(const uint4*)klp; kl4[1]=*(const uint4*)(klp+4);
        vh4[0]=*(const uint4*)vp;  vh4[1]=*(const uint4*)(vp+4);
        vl4[0]=*(const uint4*)vlp; vl4[1]=*(const uint4*)(vlp+4);
        *(uint4*)&Kh[wbase0] = kh4[0]; *(uint4*)&Kh[wbase0+4] = kh4[1];
        *(uint4*)&Kl[wbase0] = kl4[0]; *(uint4*)&Kl[wbase0+4] = kl4[1];
        *(uint4*)&Vh[wbase0] = vh4[0]; *(uint4*)&Vh[wbase0+4] = vh4[1];
        *(uint4*)&Vl[wbase0] = vl4[0]; *(uint4*)&Vl[wbase0+4] = vl4[1];
    }
    __syncthreads();

    for (int st = 0; st < nst; st++) {
        const uint32_t bufB = (st & 1) * TILEWB;
        const int s0 = st * 64;

        if (st + 1 < nst) {
            int sn = (st+1) * 64;
            const unsigned* kp = g_khh + ((size_t)bh*TT + sn + prow)*32 + pw;
            const unsigned* klp = g_khl + ((size_t)bh*TT + sn + prow)*32 + pw;
            const unsigned* vp = g_vth + ((size_t)bh*HDD + prow)*(TT/2) + sn/2 + pw;
            const unsigned* vlp = g_vtl + ((size_t)bh*HDD + prow)*(TT/2) + sn/2 + pw;
            kh4[0]=*(const uint4*)kp;  kh4[1]=*(const uint4*)(kp+4);
            kl4[0]=*(const uint4*)klp; kl4[1]=*(const uint4*)(klp+4);
            vh4[0]=*(const uint4*)vp;  vh4[1]=*(const uint4*)(vp+4);
            vl4[0]=*(const uint4*)vlp; vl4[1]=*(const uint4*)(vlp+4);
        }

        float sacc[8][4];
        #pragma unroll
        for (int i = 0; i < 8; i++)
            #pragma unroll
            for (int q = 0; q < 4; q++) sacc[i][q] = 0.f;

        // ---- S = Q K^T ----
        #pragma unroll
        for (int ks = 0; ks < 4; ks++) {
            #pragma unroll
            for (int p = 0; p < 4; p++) {
                uint32_t kd = fragBase + bufB + (p * 16 * KSTR + ks * 8) * 4;
                unsigned bbh[4], bbl[4];
                ldsm_x4(bbh[0], bbh[1], bbh[2], bbh[3], kd);
                ldsm_x4(bbl[0], bbl[1], bbl[2], bbl[3], kd + 2*TILEWB);
                unsigned h0[2] = { bbh[0], bbh[1] }, h1[2] = { bbh[2], bbh[3] };
                unsigned l0[2] = { bbl[0], bbl[1] }, l1[2] = { bbl[2], bbl[3] };
                mma_bf16(sacc[2*p],   qah[ks], h0);
                mma_bf16(sacc[2*p],   qal[ks], h0);
                mma_bf16(sacc[2*p],   qah[ks], l0);
                mma_bf16(sacc[2*p+1], qah[ks], h1);
                mma_bf16(sacc[2*p+1], qal[ks], h1);
                mma_bf16(sacc[2*p+1], qah[ks], l1);
            }
        }

        if (causal) {
            #pragma unroll
            for (int nt = 0; nt < 8; nt++) {
                int sg = s0 + nt*8 + 2*lr;
                if (sg     > trow)     sacc[nt][0] = 0.f;
                if (sg + 1 > trow)     sacc[nt][1] = 0.f;
                if (sg     > trow + 8) sacc[nt][2] = 0.f;
                if (sg + 1 > trow + 8) sacc[nt][3] = 0.f;
            }
        }
        #pragma unroll
        for (int nt = 0; nt < 8; nt++) {
            lo = fminf(lo, fminf(fminf(sacc[nt][0], sacc[nt][1]), fminf(sacc[nt][2], sacc[nt][3])));
            hi = fmaxf(hi, fmaxf(fmaxf(sacc[nt][0], sacc[nt][1]), fmaxf(sacc[nt][2], sacc[nt][3])));
        }

        // ---- U += S @ V ----
        #pragma unroll
        for (int ks = 0; ks < 4; ks++) {
            unsigned sah[4], sal[4];
            split2(sacc[2*ks  ][0], sacc[2*ks  ][1], sah[0], sal[0]);
            split2(sacc[2*ks  ][2], sacc[2*ks  ][3], sah[1], sal[1]);
            split2(sacc[2*ks+1][0], sacc[2*ks+1][1], sah[2], sal[2]);
            split2(sacc[2*ks+1][2], sacc[2*ks+1][3], sah[3], sal[3]);
            #pragma unroll
            for (int p = 0; p < 4; p++) {
                uint32_t vd = fragBase + bufB + 4*TILEWB + (p * 16 * KSTR + ks * 8) * 4;
                unsigned vvh[4], vvl[4];
                ldsm_x4(vvh[0], vvh[1], vvh[2], vvh[3], vd);
                ldsm_x4(vvl[0], vvl[1], vvl[2], vvl[3], vd + 2*TILEWB);
                unsigned h0[2] = { vvh[0], vvh[1] }, h1[2] = { vvh[2], vvh[3] };
                unsigned l0[2] = { vvl[0], vvl[1] }, l1[2] = { vvl[2], vvl[3] };
                mma_bf16(uacc[2*p],   sah, h0);
                mma_bf16(uacc[2*p],   sal, h0);
                mma_bf16(uacc[2*p],   sah, l0);
                mma_bf16(uacc[2*p+1], sah, h1);
                mma_bf16(uacc[2*p+1], sal, h1);
                mma_bf16(uacc[2*p+1], sah, l1);
            }
        }

        if (st + 1 < nst) {
            int wb = ((st+1) & 1) * TILEW + wbase0;
            *(uint4*)&Kh[wb] = kh4[0]; *(uint4*)&Kh[wb+4] = kh4[1];
            *(uint4*)&Kl[wb] = kl4[0]; *(uint4*)&Kl[wb+4] = kl4[1];
            *(uint4*)&Vh[wb] = vh4[0]; *(uint4*)&Vh[wb+4] = vh4[1];
            *(uint4*)&Vl[wb] = vl4[0]; *(uint4*)&Vl[wb+4] = vl4[1];
        }
        __syncthreads();
    }

    #pragma unroll
    for (int dt = 0; dt < 8; dt++) {
        int n = dt*8 + 2*lr;
        *(float2*)(g_ah + ((size_t)bh*TT + trow)*HDD + n)     = make_float2(uacc[dt][0], uacc[dt][1]);
        *(float2*)(g_ah + ((size_t)bh*TT + trow + 8)*HDD + n) = make_float2(uacc[dt][2], uacc[dt][3]);
    }

    #pragma unroll
    for (int o = 16; o > 0; o >>= 1) {
        lo = fminf(lo, __shfl_xor_sync(0xFFFFFFFFu, lo, o));
        hi = fmaxf(hi, __shfl_xor_sync(0xFFFFFFFFu, hi, o));
    }
    if (lane == 0) { rlo[wid] = lo; rhi[wid] = hi; }
    __syncthreads();
    if (tid == 0) {
        float l2 = rlo[0], h2 = rhi[0];
        #pragma unroll
        for (int w = 1; w < 8; w++) { l2 = fminf(l2, rlo[w]); h2 = fmaxf(h2, rhi[w]); }
        atomicMin(&g_enc_mm[0], fenc(l2));
        atomicMax(&g_enc_mm[1], fenc(h2));
    }
}

// ---------------- split heads (q,k) -> packed hi/lo [bh][t][d] ----------------
__global__ void __launch_bounds__(256) split_heads_qk(
    const float* __restrict__ qsrc, int qld,
    const float* __restrict__ ksrc, int kld)
{
    int idx = blockIdx.x * 256 + threadIdx.x;
    if (idx >= BHH*TT*32) return;
    int dw = idx & 31;
    int t  = (idx >> 5) & (TT-1);
    int bh = idx >> 16;
    int b = bh >> 3, h = bh & 7;
    size_t r = (size_t)t * BB + b;
    int c = h * HDD + 2*dw;
    float q0 = qsrc[r*qld + c] * 0.125f;
    float q1 = qsrc[r*qld + c + 1] * 0.125f;
    split2(q0, q1, g_qhh[idx], g_qhl[idx]);
    float k0 = ksrc[r*kld + c];
    float k1 = ksrc[r*kld + c + 1];
    split2(k0, k1, g_khh[idx], g_khl[idx]);
}

// ---------------- transpose V -> packed hi/lo [bh][d][t] ----------------
__global__ void __launch_bounds__(256) transpose_v(
    const float* __restrict__ vsrc, int ldv)
{
    __shared__ float tile[32][33];
    const int bh = blockIdx.z;
    const int b = bh >> 3, h = bh & 7;
    const int t0 = blockIdx.x * 32, d0 = blockIdx.y * 32;
    const int tx = threadIdx.x & 31, ty = threadIdx.x >> 5;
    #pragma unroll
    for (int j = ty; j < 32; j += 8)
        tile[j][tx] = vsrc[(size_t)((t0 + j)*BB + b) * ldv + h*HDD + d0 + tx];
    __syncthreads();
    int d = threadIdx.x >> 3;
    int twl = threadIdx.x & 7;
    #pragma unroll
    for (int rep = 0; rep < 2; rep++) {
        int tw = twl + rep*8;
        float v0 = tile[2*tw][d], v1 = tile[2*tw+1][d];
        size_t o = ((size_t)bh*HDD + d0 + d) * (TT/2) + (t0 >> 1) + tw;
        split2(v0, v1, g_vth[o], g_vtl[o]);
    }
}

// ---------------- column sums of V per (bh,d) + min/max reset (fused) ----------------
__global__ void __launch_bounds__(256) colsum_v(int causal)
{
    if (blockIdx.x == 0 && threadIdx.x == 0) {
        unsigned z = fenc(0.f);
        g_enc_mm[0] = causal ? z : 0xFFFFFFFFu;
        g_enc_mm[1] = causal ? z : 0u;
    }
    const int bh = blockIdx.x >> 3;
    const int wid = threadIdx.x >> 5, lane = threadIdx.x & 31;
    const int d = (blockIdx.x & 7) * 8 + wid;
    const uint4* ph = (const uint4*)(g_vth + ((size_t)bh*HDD + d) * (TT/2));
    const uint4* pl = (const uint4*)(g_vtl + ((size_t)bh*HDD + d) * (TT/2));
    float s = 0.f;
    #pragma unroll
    for (int i = lane; i < TT/8; i += 32) {
        uint4 h4 = ph[i], l4 = pl[i];
        float2 a = b2f(h4.x), bq = b2f(h4.y), c = b2f(h4.z), dd = b2f(h4.w);
        float2 e = b2f(l4.x), f = b2f(l4.y), g = b2f(l4.z), hh2 = b2f(l4.w);
        s += a.x+a.y + bq.x+bq.y + c.x+c.y + dd.x+dd.y
           + e.x+e.y + f.x+f.y + g.x+g.y + hh2.x+hh2.y;
    }
    #pragma unroll
    for (int o = 16; o > 0; o >>= 1) s += __shfl_xor_sync(0xFFFFFFFFu, s, o);
    if (lane == 0) g_colsum[bh*HDD + d] = s;
}

// ---------------- merge heads + normalization epilogue -> packed hi/lo ----------------
__global__ void __launch_bounds__(256) merge_heads()
{
    int idx = blockIdx.x * 256 + threadIdx.x;
    if (idx >= MR*CC/2) return;
    float mn = fdec(g_enc_mm[0]);
    float inv = 1.0f / (fdec(g_enc_mm[1]) - mn);
    float k2 = mn * inv;
    int cw = idx & 255;
    int r = idx >> 8;
    int b = r & 1;
    int t = r >> 1;
    int c = 2*cw;
    int h = c >> 6, d = c & 63;
    int bh = b*HH + h;
    float cs0 = g_colsum[bh*HDD + d], cs1 = g_colsum[bh*HDD + d + 1];
    float u0 = g_ah[((size_t)bh*TT + t)*HDD + d];
    float u1 = g_ah[((size_t)bh*TT + t)*HDD + d + 1];
    split2(inv*u0 - k2*cs0, inv*u1 - k2*cs1, g_aoh[idx], g_aol[idx]);
}

// ---------------- residual add + LayerNorm (fp32 + hi/lo out) ----------------
__global__ void __launch_bounds__(128) add_ln(
    float* __restrict__ x, const float* __restrict__ dlt,
    const float* __restrict__ g, const float* __restrict__ b)
{
    const int r = blockIdx.x;
    const int tid = threadIdx.x;
    __shared__ float sred[128];
    float4 xv = *(float4*)(x + (size_t)r*CC + tid*4);
    float4 dv = *(const float4*)(dlt + (size_t)r*CC + tid*4);
    float y0 = xv.x+dv.x, y1 = xv.y+dv.y, y2 = xv.z+dv.z, y3 = xv.w+dv.w;

    sred[tid] = y0+y1+y2+y3;
    __syncthreads();
    for (int s = 64; s > 0; s >>= 1) {
        if (tid < s) sred[tid] += sred[tid+s];
        __syncthreads();
    }
    float mu = sred[0] * (1.0f/CC);
    __syncthreads();

    float d0 = y0-mu, d1 = y1-mu, d2 = y2-mu, d3 = y3-mu;
    sred[tid] = d0*d0 + d1*d1 + d2*d2 + d3*d3;
    __syncthreads();
    for (int s = 64; s > 0; s >>= 1) {
        if (tid < s) sred[tid] += sred[tid+s];
        __syncthreads();
    }
    float rstd = rsqrtf(sred[0] * (1.0f/CC) + 1e-20f);

    float4 gv = *(const float4*)(g + tid*4);
    float4 bv = *(const float4*)(b + tid*4);
    float4 ov;
    ov.x = d0*rstd*gv.x + bv.x;
    ov.y = d1*rstd*gv.y + bv.y;
    ov.z = d2*rstd*gv.z + bv.z;
    ov.w = d3*rstd*gv.w + bv.w;
    *(float4*)(x + (size_t)r*CC + tid*4) = ov;
    int widx = r*256 + tid*2;
    split2(ov.x, ov.y, g_xh[widx], g_xl[widx]);
    split2(ov.z, ov.w, g_xh[widx+1], g_xl[widx+1]);
}

__global__ void __launch_bounds__(256) copy_out(float* __restrict__ out)
{
    int idx = blockIdx.x * 256 + threadIdx.x;
    if (idx < MR*CC) out[idx] = g_x[idx];
}

// ---------------- host orchestration ----------------
extern "C" void kernel_launch(void* const* d_in, const int* in_sizes, int n_in,
                              void* d_out, int out_size)
{
    const float* x       = (const float*)d_in[0];
    const float* enc     = (const float*)d_in[1];
    const int*   tokens  = (const int*)  d_in[2];
    const float* sWqkv   = (const float*)d_in[3];
    const float* sbqkv   = (const float*)d_in[4];
    const float* sWo     = (const float*)d_in[5];
    const float* sbo     = (const float*)d_in[6];
    const float* cWqkv   = (const float*)d_in[7];
    const float* cbqkv   = (const float*)d_in[8];
    const float* cWo     = (const float*)d_in[9];
    const float* cbo     = (const float*)d_in[10];
    const float* fc1w    = (const float*)d_in[11];
    const float* fc1b    = (const float*)d_in[12];
    const float* fc2w    = (const float*)d_in[13];
    const float* fc2b    = (const float*)d_in[14];
    const float* ln1g    = (const float*)d_in[15];
    const float* ln1b    = (const float*)d_in[16];
    const float* ln2g    = (const float*)d_in[17];
    const float* ln2b    = (const float*)d_in[18];
    const float* ln3g    = (const float*)d_in[19];
    const float* ln3b    = (const float*)d_in[20];

    static int attr_set = 0;
    if (!attr_set) {
        cudaFuncSetAttribute(attn_fused, cudaFuncAttributeMaxDynamicSharedMemorySize, SMEM_FUSED);
        cudaFuncSetAttribute(gemm_bf16s<false,false>, cudaFuncAttributeMaxDynamicSharedMemorySize, GSM_BYTES);
        cudaFuncSetAttribute(gemm_bf16s<true,true>,  cudaFuncAttributeMaxDynamicSharedMemorySize, GSM_BYTES);
        attr_set = 1;
    }

    float *px, *ptmp, *pqkv, *pkv;
    cudaGetSymbolAddress((void**)&px,   g_x);
    cudaGetSymbolAddress((void**)&ptmp, g_tmp);
    cudaGetSymbolAddress((void**)&pqkv, g_qkv);
    cudaGetSymbolAddress((void**)&pkv,  g_kv);
    unsigned *pwh, *pwl, *pxh, *pxl, *pench, *pencl, *phh, *phl, *paoh, *paol;
    cudaGetSymbolAddress((void**)&pwh, g_wh);
    cudaGetSymbolAddress((void**)&pwl, g_wl);
    cudaGetSymbolAddress((void**)&pxh, g_xh);
    cudaGetSymbolAddress((void**)&pxl, g_xl);
    cudaGetSymbolAddress((void**)&pench, g_ench);
    cudaGetSymbolAddress((void**)&pencl, g_encl);
    cudaGetSymbolAddress((void**)&phh, g_hh);
    cudaGetSymbolAddress((void**)&phl, g_hl);
    cudaGetSymbolAddress((void**)&paoh, g_aoh);
    cudaGetSymbolAddress((void**)&paol, g_aol);

    conv_weights<<<dim3(LW/256, NLAYER), 256>>>(sWqkv, sWo, cWqkv, cWo, fc1w, fc2w);
    split_f32<<<MR*CC/2/256, 256>>>(enc, pench, pencl);
    pos_embed_kernel<<<MR*CC/2/256, 256>>>(x, tokens);

    for (int l = 0; l < NLAYER; l++) {
        const unsigned* lwh = pwh + (size_t)l*LW;
        const unsigned* lwl = pwl + (size_t)l*LW;

        // ---- self-attention ----
        gemm_bf16s<false,false><<<dim3(3*CC/GBN, MR/BM), 256, GSM_BYTES>>>(
            pxh, pxl, lwh + OFF_SQKV, lwl + OFF_SQKV, sbqkv + (size_t)l*3*CC,
            pqkv, nullptr, nullptr, 3*CC, CC);
        split_heads_qk<<<BHH*TT*32/256, 256>>>(pqkv, 3*CC, pqkv + CC, 3*CC);
        transpose_v<<<dim3(TT/32, HDD/32, BHH), 256>>>(pqkv + 2*CC, 3*CC);
        colsum_v<<<BHH*8, 256>>>(1);
        attn_fused<<<dim3(TT/128, BHH), 256, SMEM_FUSED>>>(1);
        merge_heads<<<MR*CC/2/256, 256>>>();
        gemm_bf16s<false,false><<<dim3(CC/GBN, MR/BM), 256, GSM_BYTES>>>(
            paoh, paol, lwh + OFF_SWO, lwl + OFF_SWO, sbo + (size_t)l*CC,
            ptmp, nullptr, nullptr, CC, CC);
        add_ln<<<MR, 128>>>(px, ptmp, ln1g + l*CC, ln1b + l*CC);

        // ---- cross-attention ----
        gemm_bf16s<false,false><<<dim3(CC/GBN, MR/BM), 256, GSM_BYTES>>>(
            pxh, pxl, lwh + OFF_CQKV, lwl + OFF_CQKV, cbqkv + (size_t)l*3*CC,
            pqkv, nullptr, nullptr, CC, CC);
        gemm_bf16s<false,false><<<dim3(2*CC/GBN, MR/BM), 256, GSM_BYTES>>>(
            pench, pencl, lwh + OFF_CKV, lwl + OFF_CKV, cbqkv + (size_t)l*3*CC + CC,
            pkv, nullptr, nullptr, 2*CC, CC);
        split_heads_qk<<<BHH*TT*32/256, 256>>>(pqkv, CC, pkv, 2*CC);
        transpose_v<<<dim3(TT/32, HDD/32, BHH), 256>>>(pkv + CC, 2*CC);
        colsum_v<<<BHH*8, 256>>>(0);
        attn_fused<<<dim3(TT/128, BHH), 256, SMEM_FUSED>>>(0);
        merge_heads<<<MR*CC/2/256, 256>>>();
        gemm_bf16s<false,false><<<dim3(CC/GBN, MR/BM), 256, GSM_BYTES>>>(
            paoh, paol, lwh + OFF_CWO, lwl + OFF_CWO, cbo + (size_t)l*CC,
            ptmp, nullptr, nullptr, CC, CC);
        add_ln<<<MR, 128>>>(px, ptmp, ln2g + l*CC, ln2b + l*CC);

        // ---- FFN ----
        gemm_bf16s<true,true><<<dim3(FF/GBN, MR/BM), 256, GSM_BYTES>>>(
            pxh, pxl, lwh + OFF_FC1, lwl + OFF_FC1, fc1b + (size_t)l*FF,
            nullptr, phh, phl, FF, CC);
        gemm_bf16s<false,false><<<dim3(CC/GBN, MR/BM), 256, GSM_BYTES>>>(
            phh, phl, lwh + OFF_FC2, lwl + OFF_FC2, fc2b + (size_t)l*CC,
            ptmp, nullptr, nullptr, CC, FF);
        add_ln<<<MR, 128>>>(px, ptmp, ln3g + l*CC, ln3b + l*CC);
    }

    copy_out<<<MR*CC/256, 256>>>((float*)d_out);
}

// round 15
// speedup vs baseline: 1.0401x; 1.0381x over previous
#include <cuda_runtime.h>
#include <cuda_bf16.h>
#include <math.h>
#include <stdint.h>
#include <stddef.h>

// Problem dims (fixed)
#define TT 2048
#define BB 2
#define CC 512
#define HH 8
#define HDD 64
#define FF 2048
#define NLAYER 4
#define MR (TT*BB)
#define BHH (BB*HH)

#define BM 128
#define GBN 64
#define BK 32

// GEMM smem (swizzled, no padding): Ah 8KB, Al 8KB, Bh 4KB, Bl 4KB per buffer, 2 stages
#define A_AL 8192
#define A_BH 16384
#define A_BL 20480
#define GBUFSZ 24576
#define GSM_BYTES (2*GBUFSZ)

// fused attention tiling
#define KSTR 36
#define TILEW (64*KSTR)
#define TILEWB (TILEW*4)
#define SMEM_FUSED (8*TILEW*4)

// weight packing (words of bf16x2 per layer)
#define LW 2097152
#define OFF_SQKV 0
#define OFF_SWO  393216
#define OFF_CQKV 524288
#define OFF_CKV  655360
#define OFF_CWO  917504
#define OFF_FC1  1048576
#define OFF_FC2  1572864

// ---------------- scratch (device globals; no allocs allowed) ----------------
__device__ float g_x[MR*CC];
__device__ float g_tmp[MR*CC];
__device__ float g_qkv[MR*3*CC];
__device__ float g_kv[MR*2*CC];
__device__ float g_ah[BHH*TT*HDD];
__device__ float g_colsum[BHH*HDD];
__device__ unsigned g_enc_mm[2];

__device__ unsigned g_wh[4*LW], g_wl[4*LW];
__device__ unsigned g_xh[MR*CC/2], g_xl[MR*CC/2];
__device__ unsigned g_ench[MR*CC/2], g_encl[MR*CC/2];
__device__ unsigned g_hh[MR*FF/2], g_hl[MR*FF/2];
__device__ unsigned g_aoh[MR*CC/2], g_aol[MR*CC/2];
__device__ unsigned g_qhh[BHH*TT*HDD/2], g_qhl[BHH*TT*HDD/2];
__device__ unsigned g_khh[BHH*TT*HDD/2], g_khl[BHH*TT*HDD/2];
__device__ unsigned g_vth[BHH*HDD*TT/2], g_vtl[BHH*HDD*TT/2];

// ---------------- helpers ----------------
__device__ __forceinline__ unsigned fenc(float x) {
    unsigned u = __float_as_uint(x);
    return (u & 0x80000000u) ? ~u : (u | 0x80000000u);
}
__device__ __forceinline__ float fdec(unsigned e) {
    unsigned u = (e & 0x80000000u) ? (e & 0x7FFFFFFFu) : ~e;
    return __uint_as_float(u);
}
__device__ __forceinline__ void split2(float x0, float x1, unsigned &h, unsigned &l) {
    __nv_bfloat162 hb = __floats2bfloat162_rn(x0, x1);
    float r0 = x0 - __bfloat162float(hb.x);
    float r1 = x1 - __bfloat162float(hb.y);
    __nv_bfloat162 lb = __floats2bfloat162_rn(r0, r1);
    h = *reinterpret_cast<unsigned*>(&hb);
    l = *reinterpret_cast<unsigned*>(&lb);
}
__device__ __forceinline__ float2 b2f(unsigned u) {
    __nv_bfloat162 b = *reinterpret_cast<__nv_bfloat162*>(&u);
    return make_float2(__bfloat162float(b.x), __bfloat162float(b.y));
}
__device__ __forceinline__ void mma_bf16(float (&d)[4], const unsigned (&a)[4], const unsigned (&b)[2]) {
    asm volatile("mma.sync.aligned.m16n8k16.row.col.f32.bf16.bf16.f32 "
        "{%0,%1,%2,%3},{%4,%5,%6,%7},{%8,%9},{%0,%1,%2,%3};\n"
        : "+f"(d[0]), "+f"(d[1]), "+f"(d[2]), "+f"(d[3])
        : "r"(a[0]), "r"(a[1]), "r"(a[2]), "r"(a[3]), "r"(b[0]), "r"(b[1]));
}
__device__ __forceinline__ uint32_t smem_to_u32(const void* p) {
    uint32_t a;
    asm("{ .reg .u64 t; cvta.to.shared.u64 t, %1; cvt.u32.u64 %0, t; }" : "=r"(a) : "l"(p));
    return a;
}
__device__ __forceinline__ void ldsm_x4(unsigned &r0, unsigned &r1, unsigned &r2, unsigned &r3,
                                        uint32_t addr) {
    asm volatile("ldmatrix.sync.aligned.m8n8.x4.shared.b16 {%0,%1,%2,%3}, [%4];"
        : "=r"(r0), "=r"(r1), "=r"(r2), "=r"(r3) : "r"(addr));
}
#define CP_ASYNC16(dst, src) \
    asm volatile("cp.async.cg.shared.global [%0], [%1], 16;\n" :: "r"(dst), "l"(src))
#define CP_COMMIT() asm volatile("cp.async.commit_group;\n" ::: "memory")
#define CP_WAIT0()  asm volatile("cp.async.wait_group 0;\n" ::: "memory")
#define CP_WAIT1()  asm volatile("cp.async.wait_group 1;\n" ::: "memory")

// swizzled byte offset of (logical row R, 16B chunk q) inside one array
__device__ __forceinline__ uint32_t swz(int row, int q) {
    return (uint32_t)((row >> 1) * 128 + ((((row & 1) << 2) | q) ^ ((row >> 1) & 7)) * 16);
}

// ---------------- weight pre-split (once per launch) ----------------
__global__ void __launch_bounds__(256) conv_weights(
    const float* __restrict__ sW, const float* __restrict__ sWo,
    const float* __restrict__ cW, const float* __restrict__ cWo,
    const float* __restrict__ f1, const float* __restrict__ f2)
{
    int l = blockIdx.y;
    int w = blockIdx.x * 256 + threadIdx.x;
    const float* src; int wl;
    if      (w < 393216)  { src = sW  + (size_t)l*786432;  wl = w; }
    else if (w < 524288)  { src = sWo + (size_t)l*262144;  wl = w - 393216; }
    else if (w < 917504)  { src = cW  + (size_t)l*786432;  wl = w - 524288; }
    else if (w < 1048576) { src = cWo + (size_t)l*262144;  wl = w - 917504; }
    else if (w < 1572864) { src = f1  + (size_t)l*1048576; wl = w - 1048576; }
    else                  { src = f2  + (size_t)l*1048576; wl = w - 1572864; }
    float2 v = *(const float2*)(src + 2*(size_t)wl);
    unsigned h, lo;
    split2(v.x, v.y, h, lo);
    g_wh[(size_t)l*LW + w] = h;
    g_wl[(size_t)l*LW + w] = lo;
}

__global__ void __launch_bounds__(256) split_f32(
    const float* __restrict__ src, unsigned* __restrict__ dh, unsigned* __restrict__ dl)
{
    int idx = blockIdx.x * 256 + threadIdx.x;
    float2 v = *(const float2*)(src + 2*(size_t)idx);
    split2(v.x, v.y, dh[idx], dl[idx]);
}

// ---------------- positional embedding + input add ----------------
__global__ void __launch_bounds__(256) pos_embed_kernel(
    const float* __restrict__ xin, const int* __restrict__ tokens)
{
    int idx = blockIdx.x * 256 + threadIdx.x;
    if (idx >= MR*CC/2) return;
    int cw = idx & 255;
    int r = idx >> 8;
    int b = r & 1;
    int t = r >> 1;
    int c = 2*cw;
    float x0 = xin[(size_t)r*CC + c], x1 = xin[(size_t)r*CC + c + 1];
    if (tokens[b*TT + t] != 0) {
        int j0 = (c < 256) ? c : c - 256;
        float f0 = expf((float)j0 * (-9.210340371976184f / 255.0f));
        float f1 = expf((float)(j0+1) * (-9.210340371976184f / 255.0f));
        float a0 = (float)(t + 1) * f0, a1 = (float)(t + 1) * f1;
        x0 += (c < 256) ? sinf(a0) : cosf(a0);
        x1 += (c < 256) ? sinf(a1) : cosf(a1);
    }
    g_x[(size_t)r*CC + c] = x0;
    g_x[(size_t)r*CC + c + 1] = x1;
    split2(x0, x1, g_xh[idx], g_xl[idx]);
}

// ================= bf16 hi/lo TN GEMM, 128x64 tile, swizzled smem, 2-stage, 3 CTAs/SM =================
template<bool RELU, bool SPLIT>
__global__ void __launch_bounds__(256, 3) gemm_bf16s(
    const unsigned* __restrict__ Agh, const unsigned* __restrict__ Agl,
    const unsigned* __restrict__ Wgh, const unsigned* __restrict__ Wgl,
    const float* __restrict__ bias, float* __restrict__ out,
    unsigned* __restrict__ outh, unsigned* __restrict__ outl,
    int N, int K)
{
    extern __shared__ unsigned gsm[];
    const uint32_t sb = smem_to_u32(gsm);
    const int tid = threadIdx.x;
    const int m0 = blockIdx.y * BM, n0 = blockIdx.x * GBN;
    const int K2 = K >> 1;

    const unsigned* bases[4] = {
        Agh + (size_t)m0 * K2, Agl + (size_t)m0 * K2,
        Wgh + (size_t)n0 * K2, Wgl + (size_t)n0 * K2 };
    const uint32_t arrOff[4] = { 0u, A_AL, A_BH, A_BL };

    auto stage = [&](int kt, int buf) {
        uint32_t dst0 = sb + buf * GBUFSZ;
        #pragma unroll
        for (int i = 0; i < 6; i++) {
            int c = i * 256 + tid;
            int arr, u;
            if (i < 2)       { arr = 0; u = c; }
            else if (i < 4)  { arr = 1; u = c - 512; }
            else if (i == 4) { arr = 2; u = c - 1024; }
            else             { arr = 3; u = c - 1280; }
            int row = u >> 2, q = u & 3;
            const unsigned* src = bases[arr] + (size_t)row * K2 + kt * 16 + q * 4;
            uint32_t dst = dst0 + arrOff[arr] + swz(row, q);
            CP_ASYNC16(dst, src);
        }
        CP_COMMIT();
    };

    const int wid = tid >> 5, lane = tid & 31;
    const int wy = wid >> 1, wx = wid & 1;     // 4 x 2 warps, 32x32 each
    const int lq = lane >> 2, lr = lane & 3;
    const int wm = wy * 32, wn = wx * 32;

    // ldmatrix per-lane constants
    const int row_offA = ((lane >> 3) & 1) * 8 + (lane & 7);
    const int hia = (lane >> 4) & 1;
    const int r2a = row_offA >> 1, halfa = row_offA & 1;
    const uint32_t aRow = (uint32_t)(wm * 64 + r2a * 128);
    const uint32_t chA0 = (uint32_t)(((((halfa << 2) | hia)     ) ^ r2a) * 16);
    const uint32_t chA1 = (uint32_t)(((((halfa << 2) | (2 + hia))) ^ r2a) * 16);

    const int row_offB = ((lane >> 4) & 1) * 8 + (lane & 7);
    const int hib = (lane >> 3) & 1;
    const int r2b = row_offB >> 1, halfb = row_offB & 1;
    const uint32_t bRow = (uint32_t)(A_BH + wn * 64 + r2b * 128);
    const uint32_t chB0 = (uint32_t)(((((halfb << 2) | hib)     ) ^ r2b) * 16);
    const uint32_t chB1 = (uint32_t)(((((halfb << 2) | (2 + hib))) ^ r2b) * 16);

    float acc[2][4][4];
    #pragma unroll
    for (int i = 0; i < 2; i++)
        #pragma unroll
        for (int j = 0; j < 4; j++)
            #pragma unroll
            for (int q = 0; q < 4; q++) acc[i][j][q] = 0.f;

    const int KT = K / BK;
    stage(0, 0);

    for (int kt = 0; kt < KT; kt++) {
        const int buf = kt & 1;
        if (kt + 1 < KT) { stage(kt + 1, buf ^ 1); CP_WAIT1(); }
        else             { CP_WAIT0(); }
        __syncthreads();

        const uint32_t bufB = sb + buf * GBUFSZ;
        #pragma unroll
        for (int ks = 0; ks < 2; ks++) {
            const uint32_t cA = ks ? chA1 : chA0;
            const uint32_t cB = ks ? chB1 : chB0;
            unsigned ah[2][4], al_[2][4];
            #pragma unroll
            for (int mt = 0; mt < 2; mt++) {
                uint32_t ad = bufB + aRow + mt * 1024 + cA;
                ldsm_x4(ah[mt][0], ah[mt][1], ah[mt][2], ah[mt][3], ad);
                ldsm_x4(al_[mt][0], al_[mt][1], al_[mt][2], al_[mt][3], ad + A_AL);
            }
            unsigned bh_[4][2], bl_[4][2];
            #pragma unroll
            for (int p = 0; p < 2; p++) {
                uint32_t bd = bufB + bRow + p * 1024 + cB;
                ldsm_x4(bh_[2*p][0], bh_[2*p][1], bh_[2*p+1][0], bh_[2*p+1][1], bd);
                ldsm_x4(bl_[2*p][0], bl_[2*p][1], bl_[2*p+1][0], bl_[2*p+1][1], bd + 4096);
            }
            #pragma unroll
            for (int mt = 0; mt < 2; mt++)
                #pragma unroll
                for (int nt = 0; nt < 4; nt++) {
                    mma_bf16(acc[mt][nt], ah[mt],  bh_[nt]);
                    mma_bf16(acc[mt][nt], ah[mt],  bl_[nt]);
                    mma_bf16(acc[mt][nt], al_[mt], bh_[nt]);
                }
        }
        __syncthreads();
    }

    #pragma unroll
    for (int mt = 0; mt < 2; mt++) {
        int m = m0 + wm + mt*16 + lq;
        #pragma unroll
        for (int nt = 0; nt < 4; nt++) {
            int n = n0 + wn + nt*8 + 2*lr;
            float2 bv = *(const float2*)(bias + n);
            float v0 = acc[mt][nt][0] + bv.x;
            float v1 = acc[mt][nt][1] + bv.y;
            float v2 = acc[mt][nt][2] + bv.x;
            float v3 = acc[mt][nt][3] + bv.y;
            if (RELU) { v0=fmaxf(v0,0.f); v1=fmaxf(v1,0.f); v2=fmaxf(v2,0.f); v3=fmaxf(v3,0.f); }
            if (SPLIT) {
                split2(v0, v1, outh[((size_t)m*N + n) >> 1], outl[((size_t)m*N + n) >> 1]);
                split2(v2, v3, outh[((size_t)(m+8)*N + n) >> 1], outl[((size_t)(m+8)*N + n) >> 1]);
            } else {
                *(float2*)(out + (size_t)m*N + n)     = make_float2(v0, v1);
                *(float2*)(out + (size_t)(m+8)*N + n) = make_float2(v2, v3);
            }
        }
    }
}

// ================= fused attention: U = (masked scores) @ V (R10 version) =================
__global__ void __launch_bounds__(256, 1) attn_fused(int causal)
{
    extern __shared__ unsigned sm[];
    unsigned* Kh = sm;
    unsigned* Kl = sm + 2*TILEW;
    unsigned* Vh = sm + 4*TILEW;
    unsigned* Vl = sm + 6*TILEW;
    __shared__ float rlo[8], rhi[8];
    const uint32_t smb = smem_to_u32(sm);

    const int bh = blockIdx.y;
    const int t0 = (gridDim.x - 1 - blockIdx.x) * 128;
    const int tid = threadIdx.x;
    const int wid = tid >> 5, lane = tid & 31;
    const int lq = lane >> 2, lr = lane & 3;
    const int trow = t0 + wid*16 + lq;

    const int row_offB = ((lane >> 4) & 1) * 8 + (lane & 7);
    const int word_offB = ((lane >> 3) & 1) * 4;
    const uint32_t fragBase = smb + (row_offB * KSTR + word_offB) * 4;

    unsigned qah[4][4], qal[4][4];
    {
        const size_t base = ((size_t)bh*TT + trow) * 32;
        #pragma unroll
        for (int ks = 0; ks < 4; ks++) {
            int o = ks*8 + lr;
            qah[ks][0] = g_qhh[base + o];        qal[ks][0] = g_qhl[base + o];
            qah[ks][1] = g_qhh[base + 256 + o];  qal[ks][1] = g_qhl[base + 256 + o];
            qah[ks][2] = g_qhh[base + o + 4];    qal[ks][2] = g_qhl[base + o + 4];
            qah[ks][3] = g_qhh[base + 256 + o + 4]; qal[ks][3] = g_qhl[base + 256 + o + 4];
        }
    }

    float uacc[8][4];
    #pragma unroll
    for (int i = 0; i < 8; i++)
        #pragma unroll
        for (int q = 0; q < 4; q++) uacc[i][q] = 0.f;

    float lo = 3.4e38f, hi = -3.4e38f;
    const int nst = causal ? (t0/64 + 2) : (TT/64);

    const int prow = tid >> 2;
    const int pw = (tid & 3) * 8;
    const int wbase0 = prow*KSTR + pw;

    uint4 kh4[2], kl4[2], vh4[2], vl4[2];
    {
        const unsigned* kp = g_khh + ((size_t)bh*TT + prow)*32 + pw;
        const unsigned* klp = g_khl + ((size_t)bh*TT + prow)*32 + pw;
        const unsigned* vp = g_vth + ((size_t)bh*HDD + prow)*(TT/2) + pw;
        const unsigned* vlp = g_vtl + ((size_t)bh*HDD + prow)*(TT/2) + pw;
        kh4[0]=*(const uint4*)kp;  kh4[1]=*(const uint4*)(kp+4);
        kl4[0]=*(const uint4*)klp; kl4[1]=*(const uint4*)(klp+4);
        vh4[0]=*(const uint4*)vp;  vh4[1]=*(const uint4*)(vp+4);
        vl4[0]=*(const uint4*)vlp; vl4[1]=*(const uint4*)(vlp+4);
        *(uint4*)&Kh[wbase0] = kh4[0]; *(uint4*)&Kh[wbase0+4] = kh4[1];
        *(uint4*)&Kl[wbase0] = kl4[0]; *(uint4*)&Kl[wbase0+4] = kl4[1];
        *(uint4*)&Vh[wbase0] = vh4[0]; *(uint4*)&Vh[wbase0+4] = vh4[1];
        *(uint4*)&Vl[wbase0] = vl4[0]; *(uint4*)&Vl[wbase0+4] = vl4[1];
    }
    __syncthreads();

    for (int st = 0; st < nst; st++) {
        const uint32_t bufB = (st & 1) * TILEWB;
        const int s0 = st * 64;

        if (st + 1 < nst) {
            int sn = (st+1) * 64;
            const unsigned* kp = g_khh + ((size_t)bh*TT + sn + prow)*32 + pw;
            const unsigned* klp = g_khl + ((size_t)bh*TT + sn + prow)*32 + pw;
            const unsigned* vp = g_vth + ((size_t)bh*HDD + prow)*(TT/2) + sn/2 + pw;
            const unsigned* vlp = g_vtl + ((size_t)bh*HDD + prow)*(TT/2) + sn/2 + pw;
            kh4[0]=*(const uint4*)kp;  kh4[1]=*(const uint4*)(kp+4);
            kl4[0]=*(const uint4*)klp; kl4[1]=*(const uint4*)(klp+4);
            vh4[0]=*(const uint4*)vp;  vh4[1]=*(const uint4*)(vp+4);
            vl4[0]=*(const uint4*)vlp; vl4[1]=*(const uint4*)(vlp+4);
        }

        float sacc[8][4];
        #pragma unroll
        for (int i = 0; i < 8; i++)
            #pragma unroll
            for (int q = 0; q < 4; q++) sacc[i][q] = 0.f;

        // ---- S = Q K^T ----
        #pragma unroll
        for (int ks = 0; ks < 4; ks++) {
            #pragma unroll
            for (int p = 0; p < 4; p++) {
                uint32_t kd = fragBase + bufB + (p * 16 * KSTR + ks * 8) * 4;
                unsigned bbh[4], bbl[4];
                ldsm_x4(bbh[0], bbh[1], bbh[2], bbh[3], kd);
                ldsm_x4(bbl[0], bbl[1], bbl[2], bbl[3], kd + 2*TILEWB);
                unsigned h0[2] = { bbh[0], bbh[1] }, h1[2] = { bbh[2], bbh[3] };
                unsigned l0[2] = { bbl[0], bbl[1] }, l1[2] = { bbl[2], bbl[3] };
                mma_bf16(sacc[2*p],   qah[ks], h0);
                mma_bf16(sacc[2*p],   qal[ks], h0);
                mma_bf16(sacc[2*p],   qah[ks], l0);
                mma_bf16(sacc[2*p+1], qah[ks], h1);
                mma_bf16(sacc[2*p+1], qal[ks], h1);
                mma_bf16(sacc[2*p+1], qah[ks], l1);
            }
        }

        if (causal) {
            #pragma unroll
            for (int nt = 0; nt < 8; nt++) {
                int sg = s0 + nt*8 + 2*lr;
                if (sg     > trow)     sacc[nt][0] = 0.f;
                if (sg + 1 > trow)     sacc[nt][1] = 0.f;
                if (sg     > trow + 8) sacc[nt][2] = 0.f;
                if (sg + 1 > trow + 8) sacc[nt][3] = 0.f;
            }
        }
        #pragma unroll
        for (int nt = 0; nt < 8; nt++) {
            lo = fminf(lo, fminf(fminf(sacc[nt][0], sacc[nt][1]), fminf(sacc[nt][2], sacc[nt][3])));
            hi = fmaxf(hi, fmaxf(fmaxf(sacc[nt][0], sacc[nt][1]), fmaxf(sacc[nt][2], sacc[nt][3])));
        }

        // ---- U += S @ V ----
        #pragma unroll
        for (int ks = 0; ks < 4; ks++) {
            unsigned sah[4], sal[4];
            split2(sacc[2*ks  ][0], sacc[2*ks  ][1], sah[0], sal[0]);
            split2(sacc[2*ks  ][2], sacc[2*ks  ][3], sah[1], sal[1]);
            split2(sacc[2*ks+1][0], sacc[2*ks+1][1], sah[2], sal[2]);
            split2(sacc[2*ks+1][2], sacc[2*ks+1][3], sah[3], sal[3]);
            #pragma unroll
            for (int p = 0; p < 4; p++) {
                uint32_t vd = fragBase + bufB + 4*TILEWB + (p * 16 * KSTR + ks * 8) * 4;
                unsigned vvh[4], vvl[4];
                ldsm_x4(vvh[0], vvh[1], vvh[2], vvh[3], vd);
                ldsm_x4(vvl[0], vvl[1], vvl[2], vvl[3], vd + 2*TILEWB);
                unsigned h0[2] = { vvh[0], vvh[1] }, h1[2] = { vvh[2], vvh[3] };
                unsigned l0[2] = { vvl[0], vvl[1] }, l1[2] = { vvl[2], vvl[3] };
                mma_bf16(uacc[2*p],   sah, h0);
                mma_bf16(uacc[2*p],   sal, h0);
                mma_bf16(uacc[2*p],   sah, l0);
                mma_bf16(uacc[2*p+1], sah, h1);
                mma_bf16(uacc[2*p+1], sal, h1);
                mma_bf16(uacc[2*p+1], sah, l1);
            }
        }

        if (st + 1 < nst) {
            int wb = ((st+1) & 1) * TILEW + wbase0;
            *(uint4*)&Kh[wb] = kh4[0]; *(uint4*)&Kh[wb+4] = kh4[1];
            *(uint4*)&Kl[wb] = kl4[0]; *(uint4*)&Kl[wb+4] = kl4[1];
            *(uint4*)&Vh[wb] = vh4[0]; *(uint4*)&Vh[wb+4] = vh4[1];
            *(uint4*)&Vl[wb] = vl4[0]; *(uint4*)&Vl[wb+4] = vl4[1];
        }
        __syncthreads();
    }

    #pragma unroll
    for (int dt = 0; dt < 8; dt++) {
        int n = dt*8 + 2*lr;
        *(float2*)(g_ah + ((size_t)bh*TT + trow)*HDD + n)     = make_float2(uacc[dt][0], uacc[dt][1]);
        *(float2*)(g_ah + ((size_t)bh*TT + trow + 8)*HDD + n) = make_float2(uacc[dt][2], uacc[dt][3]);
    }

    #pragma unroll
    for (int o = 16; o > 0; o >>= 1) {
        lo = fminf(lo, __shfl_xor_sync(0xFFFFFFFFu, lo, o));
        hi = fmaxf(hi, __shfl_xor_sync(0xFFFFFFFFu, hi, o));
    }
    if (lane == 0) { rlo[wid] = lo; rhi[wid] = hi; }
    __syncthreads();
    if (tid == 0) {
        float l2 = rlo[0], h2 = rhi[0];
        #pragma unroll
        for (int w = 1; w < 8; w++) { l2 = fminf(l2, rlo[w]); h2 = fmaxf(h2, rhi[w]); }
        atomicMin(&g_enc_mm[0], fenc(l2));
        atomicMax(&g_enc_mm[1], fenc(h2));
    }
}

// ---------------- fused prep: split heads q/k + transpose V + min/max reset ----------------
// blocks [0, 4096): split_heads; blocks [4096, 6144): transpose_v
__global__ void __launch_bounds__(256) prep_attn(
    const float* __restrict__ qsrc, int qld,
    const float* __restrict__ ksrc, int kld,
    const float* __restrict__ vsrc, int vld,
    int causal)
{
    if (blockIdx.x == 0 && threadIdx.x == 0) {
        unsigned z = fenc(0.f);
        g_enc_mm[0] = causal ? z : 0xFFFFFFFFu;
        g_enc_mm[1] = causal ? z : 0u;
    }
    if (blockIdx.x < 4096) {
        int idx = blockIdx.x * 256 + threadIdx.x;
        int dw = idx & 31;
        int t  = (idx >> 5) & (TT-1);
        int bh = idx >> 16;
        int b = bh >> 3, h = bh & 7;
        size_t r = (size_t)t * BB + b;
        int c = h * HDD + 2*dw;
        float q0 = qsrc[r*qld + c] * 0.125f;
        float q1 = qsrc[r*qld + c + 1] * 0.125f;
        split2(q0, q1, g_qhh[idx], g_qhl[idx]);
        float k0 = ksrc[r*kld + c];
        float k1 = ksrc[r*kld + c + 1];
        split2(k0, k1, g_khh[idx], g_khl[idx]);
    } else {
        __shared__ float tile[32][33];
        int bb = blockIdx.x - 4096;
        const int t0 = (bb & 63) * 32;
        const int d0 = ((bb >> 6) & 1) * 32;
        const int bh = bb >> 7;
        const int b = bh >> 3, h = bh & 7;
        const int tx = threadIdx.x & 31, ty = threadIdx.x >> 5;
        #pragma unroll
        for (int j = ty; j < 32; j += 8)
            tile[j][tx] = vsrc[(size_t)((t0 + j)*BB + b) * vld + h*HDD + d0 + tx];
        __syncthreads();
        int d = threadIdx.x >> 3;
        int twl = threadIdx.x & 7;
        #pragma unroll
        for (int rep = 0; rep < 2; rep++) {
            int tw = twl + rep*8;
            float v0 = tile[2*tw][d], v1 = tile[2*tw+1][d];
            size_t o = ((size_t)bh*HDD + d0 + d) * (TT/2) + (t0 >> 1) + tw;
            split2(v0, v1, g_vth[o], g_vtl[o]);
        }
    }
}

// ---------------- column sums of V per (bh,d) ----------------
__global__ void __launch_bounds__(256) colsum_v()
{
    const int bh = blockIdx.x >> 3;
    const int wid = threadIdx.x >> 5, lane = threadIdx.x & 31;
    const int d = (blockIdx.x & 7) * 8 + wid;
    const uint4* ph = (const uint4*)(g_vth + ((size_t)bh*HDD + d) * (TT/2));
    const uint4* pl = (const uint4*)(g_vtl + ((size_t)bh*HDD + d) * (TT/2));
    float s = 0.f;
    #pragma unroll
    for (int i = lane; i < TT/8; i += 32) {
        uint4 h4 = ph[i], l4 = pl[i];
        float2 a = b2f(h4.x), bq = b2f(h4.y), c = b2f(h4.z), dd = b2f(h4.w);
        float2 e = b2f(l4.x), f = b2f(l4.y), g = b2f(l4.z), hh2 = b2f(l4.w);
        s += a.x+a.y + bq.x+bq.y + c.x+c.y + dd.x+dd.y
           + e.x+e.y + f.x+f.y + g.x+g.y + hh2.x+hh2.y;
    }
    #pragma unroll
    for (int o = 16; o > 0; o >>= 1) s += __shfl_xor_sync(0xFFFFFFFFu, s, o);
    if (lane == 0) g_colsum[bh*HDD + d] = s;
}

// ---------------- merge heads + normalization epilogue -> packed hi/lo ----------------
__global__ void __launch_bounds__(256) merge_heads()
{
    int idx = blockIdx.x * 256 + threadIdx.x;
    if (idx >= MR*CC/2) return;
    float mn = fdec(g_enc_mm[0]);
    float inv = 1.0f / (fdec(g_enc_mm[1]) - mn);
    float k2 = mn * inv;
    int cw = idx & 255;
    int r = idx >> 8;
    int b = r & 1;
    int t = r >> 1;
    int c = 2*cw;
    int h = c >> 6, d = c & 63;
    int bh = b*HH + h;
    float cs0 = g_colsum[bh*HDD + d], cs1 = g_colsum[bh*HDD + d + 1];
    float u0 = g_ah[((size_t)bh*TT + t)*HDD + d];
    float u1 = g_ah[((size_t)bh*TT + t)*HDD + d + 1];
    split2(inv*u0 - k2*cs0, inv*u1 - k2*cs1, g_aoh[idx], g_aol[idx]);
}

// ---------------- residual add + LayerNorm (fp32 + hi/lo out, optional final out) ----------------
__global__ void __launch_bounds__(128) add_ln(
    float* __restrict__ x, const float* __restrict__ dlt,
    const float* __restrict__ g, const float* __restrict__ b,
    float* __restrict__ outp)
{
    const int r = blockIdx.x;
    const int tid = threadIdx.x;
    __shared__ float sred[128];
    float4 xv = *(float4*)(x + (size_t)r*CC + tid*4);
    float4 dv = *(const float4*)(dlt + (size_t)r*CC + tid*4);
    float y0 = xv.x+dv.x, y1 = xv.y+dv.y, y2 = xv.z+dv.z, y3 = xv.w+dv.w;

    sred[tid] = y0+y1+y2+y3;
    __syncthreads();
    for (int s = 64; s > 0; s >>= 1) {
        if (tid < s) sred[tid] += sred[tid+s];
        __syncthreads();
    }
    float mu = sred[0] * (1.0f/CC);
    __syncthreads();

    float d0 = y0-mu, d1 = y1-mu, d2 = y2-mu, d3 = y3-mu;
    sred[tid] = d0*d0 + d1*d1 + d2*d2 + d3*d3;
    __syncthreads();
    for (int s = 64; s > 0; s >>= 1) {
        if (tid < s) sred[tid] += sred[tid+s];
        __syncthreads();
    }
    float rstd = rsqrtf(sred[0] * (1.0f/CC) + 1e-20f);

    float4 gv = *(const float4*)(g + tid*4);
    float4 bv = *(const float4*)(b + tid*4);
    float4 ov;
    ov.x = d0*rstd*gv.x + bv.x;
    ov.y = d1*rstd*gv.y + bv.y;
    ov.z = d2*rstd*gv.z + bv.z;
    ov.w = d3*rstd*gv.w + bv.w;
    *(float4*)(x + (size_t)r*CC + tid*4) = ov;
    if (outp) *(float4*)(outp + (size_t)r*CC + tid*4) = ov;
    int widx = r*256 + tid*2;
    split2(ov.x, ov.y, g_xh[widx], g_xl[widx]);
    split2(ov.z, ov.w, g_xh[widx+1], g_xl[widx+1]);
}

// ---------------- host orchestration ----------------
extern "C" void kernel_launch(void* const* d_in, const int* in_sizes, int n_in,
                              void* d_out, int out_size)
{
    const float* x       = (const float*)d_in[0];
    const float* enc     = (const float*)d_in[1];
    const int*   tokens  = (const int*)  d_in[2];
    const float* sWqkv   = (const float*)d_in[3];
    const float* sbqkv   = (const float*)d_in[4];
    const float* sWo     = (const float*)d_in[5];
    const float* sbo     = (const float*)d_in[6];
    const float* cWqkv   = (const float*)d_in[7];
    const float* cbqkv   = (const float*)d_in[8];
    const float* cWo     = (const float*)d_in[9];
    const float* cbo     = (const float*)d_in[10];
    const float* fc1w    = (const float*)d_in[11];
    const float* fc1b    = (const float*)d_in[12];
    const float* fc2w    = (const float*)d_in[13];
    const float* fc2b    = (const float*)d_in[14];
    const float* ln1g    = (const float*)d_in[15];
    const float* ln1b    = (const float*)d_in[16];
    const float* ln2g    = (const float*)d_in[17];
    const float* ln2b    = (const float*)d_in[18];
    const float* ln3g    = (const float*)d_in[19];
    const float* ln3b    = (const float*)d_in[20];

    static int attr_set = 0;
    if (!attr_set) {
        cudaFuncSetAttribute(attn_fused, cudaFuncAttributeMaxDynamicSharedMemorySize, SMEM_FUSED);
        cudaFuncSetAttribute(gemm_bf16s<false,false>, cudaFuncAttributeMaxDynamicSharedMemorySize, GSM_BYTES);
        cudaFuncSetAttribute(gemm_bf16s<true,true>,  cudaFuncAttributeMaxDynamicSharedMemorySize, GSM_BYTES);
        attr_set = 1;
    }

    float *px, *ptmp, *pqkv, *pkv;
    cudaGetSymbolAddress((void**)&px,   g_x);
    cudaGetSymbolAddress((void**)&ptmp, g_tmp);
    cudaGetSymbolAddress((void**)&pqkv, g_qkv);
    cudaGetSymbolAddress((void**)&pkv,  g_kv);
    unsigned *pwh, *pwl, *pxh, *pxl, *pench, *pencl, *phh, *phl, *paoh, *paol;
    cudaGetSymbolAddress((void**)&pwh, g_wh);
    cudaGetSymbolAddress((void**)&pwl, g_wl);
    cudaGetSymbolAddress((void**)&pxh, g_xh);
    cudaGetSymbolAddress((void**)&pxl, g_xl);
    cudaGetSymbolAddress((void**)&pench, g_ench);
    cudaGetSymbolAddress((void**)&pencl, g_encl);
    cudaGetSymbolAddress((void**)&phh, g_hh);
    cudaGetSymbolAddress((void**)&phl, g_hl);
    cudaGetSymbolAddress((void**)&paoh, g_aoh);
    cudaGetSymbolAddress((void**)&paol, g_aol);

    conv_weights<<<dim3(LW/256, NLAYER), 256>>>(sWqkv, sWo, cWqkv, cWo, fc1w, fc2w);
    split_f32<<<MR*CC/2/256, 256>>>(enc, pench, pencl);
    pos_embed_kernel<<<MR*CC/2/256, 256>>>(x, tokens);

    for (int l = 0; l < NLAYER; l++) {
        const unsigned* lwh = pwh + (size_t)l*LW;
        const unsigned* lwl = pwl + (size_t)l*LW;

        // ---- self-attention ----
        gemm_bf16s<false,false><<<dim3(3*CC/GBN, MR/BM), 256, GSM_BYTES>>>(
            pxh, pxl, lwh + OFF_SQKV, lwl + OFF_SQKV, sbqkv + (size_t)l*3*CC,
            pqkv, nullptr, nullptr, 3*CC, CC);
        prep_attn<<<6144, 256>>>(pqkv, 3*CC, pqkv + CC, 3*CC, pqkv + 2*CC, 3*CC, 1);
        colsum_v<<<BHH*8, 256>>>();
        attn_fused<<<dim3(TT/128, BHH), 256, SMEM_FUSED>>>(1);
        merge_heads<<<MR*CC/2/256, 256>>>();
        gemm_bf16s<false,false><<<dim3(CC/GBN, MR/BM), 256, GSM_BYTES>>>(
            paoh, paol, lwh + OFF_SWO, lwl + OFF_SWO, sbo + (size_t)l*CC,
            ptmp, nullptr, nullptr, CC, CC);
        add_ln<<<MR, 128>>>(px, ptmp, ln1g + l*CC, ln1b + l*CC, nullptr);

        // ---- cross-attention ----
        gemm_bf16s<false,false><<<dim3(CC/GBN, MR/BM), 256, GSM_BYTES>>>(
            pxh, pxl, lwh + OFF_CQKV, lwl + OFF_CQKV, cbqkv + (size_t)l*3*CC,
            pqkv, nullptr, nullptr, CC, CC);
        gemm_bf16s<false,false><<<dim3(2*CC/GBN, MR/BM), 256, GSM_BYTES>>>(
            pench, pencl, lwh + OFF_CKV, lwl + OFF_CKV, cbqkv + (size_t)l*3*CC + CC,
            pkv, nullptr, nullptr, 2*CC, CC);
        prep_attn<<<6144, 256>>>(pqkv, CC, pkv, 2*CC, pkv + CC, 2*CC, 0);
        colsum_v<<<BHH*8, 256>>>();
        attn_fused<<<dim3(TT/128, BHH), 256, SMEM_FUSED>>>(0);
        merge_heads<<<MR*CC/2/256, 256>>>();
        gemm_bf16s<false,false><<<dim3(CC/GBN, MR/BM), 256, GSM_BYTES>>>(
            paoh, paol, lwh + OFF_CWO, lwl + OFF_CWO, cbo + (size_t)l*CC,
            ptmp, nullptr, nullptr, CC, CC);
        add_ln<<<MR, 128>>>(px, ptmp, ln2g + l*CC, ln2b + l*CC, nullptr);

        // ---- FFN ----
        gemm_bf16s<true,true><<<dim3(FF/GBN, MR/BM), 256, GSM_BYTES>>>(
            pxh, pxl, lwh + OFF_FC1, lwl + OFF_FC1, fc1b + (size_t)l*FF,
            nullptr, phh, phl, FF, CC);
        gemm_bf16s<false,false><<<dim3(CC/GBN, MR/BM), 256, GSM_BYTES>>>(
            phh, phl, lwh + OFF_FC2, lwl + OFF_FC2, fc2b + (size_t)l*CC,
            ptmp, nullptr, nullptr, CC, FF);
        add_ln<<<MR, 128>>>(px, ptmp, ln3g + l*CC, ln3b + l*CC,
                            (l == NLAYER-1) ? (float*)d_out : nullptr);
    }
}